// round 12
// baseline (speedup 1.0000x reference)
#include <cuda_runtime.h>
#include <cuda_bf16.h>
#include <cstdint>

// Problem constants
#define BB 2
#define LL 2048
#define DD 1024
#define HH 16
#define HD 64
#define MM (BB * LL)   // 4096 rows

// ---------------------------------------------------------------------------
// Scratch (device globals; no allocations allowed). All split-bf16 pairs.
// ---------------------------------------------------------------------------
__device__ __align__(1024) __nv_bfloat16 g_xh[MM * DD], g_xl[MM * DD];
__device__ __align__(1024) __nv_bfloat16 g_qh[MM * DD], g_ql[MM * DD];
__device__ __align__(1024) __nv_bfloat16 g_kh[MM * DD], g_kl[MM * DD];
__device__ __align__(1024) __nv_bfloat16 g_vh[MM * DD], g_vl[MM * DD];
__device__ __align__(1024) __nv_bfloat16 g_ah[MM * DD], g_al[MM * DD];
__device__ __align__(1024) __nv_bfloat16 g_wh[4][DD * DD], g_wl[4][DD * DD];

// ---------------------------------------------------------------------------
// Helpers (base sm_103-safe: mma.sync / ldmatrix / cp.async only)
// ---------------------------------------------------------------------------
__device__ __forceinline__ uint32_t smem_u32(const void* p) {
    uint32_t a;
    asm("{ .reg .u64 t; cvta.to.shared.u64 t, %1; cvt.u32.u64 %0, t; }" : "=r"(a) : "l"(p));
    return a;
}
__device__ __forceinline__ void cpa16(uint32_t dst, const void* src) {
    asm volatile("cp.async.cg.shared.global [%0], [%1], 16;" :: "r"(dst), "l"(src));
}
#define CP_COMMIT() asm volatile("cp.async.commit_group;" ::: "memory")
template <int N>
__device__ __forceinline__ void cp_wait() {
    asm volatile("cp.async.wait_group %0;" :: "n"(N) : "memory");
}
__device__ __forceinline__ void ldsm_x4(uint32_t (&r)[4], uint32_t addr) {
    asm volatile("ldmatrix.sync.aligned.m8n8.x4.shared.b16 {%0,%1,%2,%3}, [%4];"
                 : "=r"(r[0]), "=r"(r[1]), "=r"(r[2]), "=r"(r[3]) : "r"(addr));
}
__device__ __forceinline__ void ldsm_x4_t(uint32_t (&r)[4], uint32_t addr) {
    asm volatile("ldmatrix.sync.aligned.m8n8.x4.trans.shared.b16 {%0,%1,%2,%3}, [%4];"
                 : "=r"(r[0]), "=r"(r[1]), "=r"(r[2]), "=r"(r[3]) : "r"(addr));
}
__device__ __forceinline__ void mma16816(float (&d)[4], const uint32_t (&a)[4],
                                         uint32_t b0, uint32_t b1) {
    asm volatile(
        "mma.sync.aligned.m16n8k16.row.col.f32.bf16.bf16.f32 "
        "{%0,%1,%2,%3}, {%4,%5,%6,%7}, {%8,%9}, {%0,%1,%2,%3};"
        : "+f"(d[0]), "+f"(d[1]), "+f"(d[2]), "+f"(d[3])
        : "r"(a[0]), "r"(a[1]), "r"(a[2]), "r"(a[3]), "r"(b0), "r"(b1));
}
__device__ __forceinline__ uint32_t pack2(float lo, float hi) {
    __nv_bfloat162 t = __floats2bfloat162_rn(lo, hi);
    return *(uint32_t*)&t;
}
__device__ __forceinline__ void split_pack(float v0, float v1, uint32_t& h, uint32_t& l) {
    __nv_bfloat16 h0 = __float2bfloat16(v0), h1 = __float2bfloat16(v1);
    float l0 = v0 - __bfloat162float(h0), l1 = v1 - __bfloat162float(h1);
    __nv_bfloat162 hp; hp.x = h0; hp.y = h1;
    h = *(uint32_t*)&hp;
    l = pack2(l0, l1);
}

// ---------------------------------------------------------------------------
// Split-bf16 mma.sync GEMM: C[M,N] = A[M,K] * Wt[N,K]^T
// R11: CTA tile 128x128, BK=32, 3-stage ring, one barrier per chunk.
// 8 warps, warp tile 32x64. 64B rows, XOR swizzle. 2 CTAs/SM (96KB, <=128 regs).
// ---------------------------------------------------------------------------
#define GA_SZ (128 * 32 * 2)        // 8192 B per array (A and B same shape)
#define GK_STAGE (4 * GA_SZ)        // 32768 B (Ah, Al, Bh, Bl)
#define GEMM_SMEM (3 * GK_STAGE)    // 98304 B

__device__ __forceinline__ uint32_t gsw(int row, int unit) {  // 64B-row swizzle
    return (uint32_t)(row * 64 + ((unit ^ ((row >> 1) & 3)) << 4));
}

template <bool SPLIT_OUT>
__global__ __launch_bounds__(256, 2) void gemm_mma(
    const __nv_bfloat16* __restrict__ Ah, const __nv_bfloat16* __restrict__ Al,
    const __nv_bfloat16* __restrict__ Bh0, const __nv_bfloat16* __restrict__ Bl0,
    __nv_bfloat16* __restrict__ Ch0, __nv_bfloat16* __restrict__ Cl0,
    __nv_bfloat16* __restrict__ Ch1, __nv_bfloat16* __restrict__ Cl1,
    __nv_bfloat16* __restrict__ Ch2, __nv_bfloat16* __restrict__ Cl2,
    float* __restrict__ Cf) {
    extern __shared__ char smc[];
    const uint32_t smb = smem_u32(smc);
    const int tid = threadIdx.x, lane = tid & 31, wid = tid >> 5;
    const int wm = (wid & 3) * 32, wn = (wid >> 2) * 64;
    const int bm = blockIdx.y * 128, bn = blockIdx.x * 128;
    const int z = blockIdx.z;
    const int g = lane >> 2, tig = lane & 3;

    const __nv_bfloat16* Bh = Bh0 + (size_t)z * DD * DD;
    const __nv_bfloat16* Bl = Bl0 + (size_t)z * DD * DD;
    __nv_bfloat16* Ch = (z == 0) ? Ch0 : (z == 1) ? Ch1 : Ch2;
    __nv_bfloat16* Cl = (z == 0) ? Cl0 : (z == 1) ? Cl1 : Cl2;
    const float scale = (SPLIT_OUT && z == 0) ? 0.125f : 1.0f;

    float acc[2][8][4];
#pragma unroll
    for (int a = 0; a < 2; a++)
#pragma unroll
        for (int b = 0; b < 8; b++)
#pragma unroll
            for (int c = 0; c < 4; c++) acc[a][b][c] = 0.0f;

    // Stage loader: 2048 16B units (A: 1024, B: 1024); 256 threads x 8.
    auto load_stage = [&](int s, int c) {
        const uint32_t sb = smb + s * GK_STAGE;
#pragma unroll
        for (int i = 0; i < 8; i++) {
            int u = tid + i * 256;
            if (u < 1024) {
                int arr = u >> 9;
                int w = u & 511;
                int row = w >> 2, un = w & 3;
                const __nv_bfloat16* src = (arr ? Al : Ah) + (size_t)(bm + row) * DD + c * 32 + un * 8;
                cpa16(sb + arr * GA_SZ + gsw(row, un), src);
            } else {
                int u2 = u - 1024;
                int arr = u2 >> 9;
                int w = u2 & 511;
                int row = w >> 2, un = w & 3;
                const __nv_bfloat16* src = (arr ? Bl : Bh) + (size_t)(bn + row) * DD + c * 32 + un * 8;
                cpa16(sb + 2 * GA_SZ + arr * GA_SZ + gsw(row, un), src);
            }
        }
    };

    load_stage(0, 0);
    CP_COMMIT();
    load_stage(1, 1);
    CP_COMMIT();

    for (int c = 0; c < 32; c++) {
        cp_wait<1>();
        __syncthreads();   // chunk c published; all reads of slot (c+2)%3 done
        // Prefetch chunk c+2 into the freed slot; overlaps this chunk's compute.
        if (c + 2 < 32) load_stage((c + 2) % 3, c + 2);
        CP_COMMIT();

        const uint32_t sA_h = smb + (c % 3) * GK_STAGE;
        const uint32_t sA_l = sA_h + GA_SZ;
        const uint32_t sB_h = sA_h + 2 * GA_SZ;
        const uint32_t sB_l = sB_h + GA_SZ;
#pragma unroll
        for (int j = 0; j < 2; j++) {
            uint32_t ah4[2][4], al4[2][4];
#pragma unroll
            for (int mi = 0; mi < 2; mi++) {
                int row = wm + 16 * mi + (lane & 15);
                int un = 2 * j + (lane >> 4);
                uint32_t off = gsw(row, un);
                ldsm_x4(ah4[mi], sA_h + off);
                ldsm_x4(al4[mi], sA_l + off);
            }
#pragma unroll
            for (int p = 0; p < 4; p++) {
                int row = wn + 16 * p + ((lane >> 4) << 3) + (lane & 7);
                int un = 2 * j + ((lane >> 3) & 1);
                uint32_t off = gsw(row, un);
                uint32_t bh_t[4], bl_t[4];
                ldsm_x4(bh_t, sB_h + off);
                ldsm_x4(bl_t, sB_l + off);
#pragma unroll
                for (int mi = 0; mi < 2; mi++) {
                    mma16816(acc[mi][2 * p],     ah4[mi], bh_t[0], bh_t[1]);
                    mma16816(acc[mi][2 * p + 1], ah4[mi], bh_t[2], bh_t[3]);
                    mma16816(acc[mi][2 * p],     ah4[mi], bl_t[0], bl_t[1]);
                    mma16816(acc[mi][2 * p + 1], ah4[mi], bl_t[2], bl_t[3]);
                    mma16816(acc[mi][2 * p],     al4[mi], bh_t[0], bh_t[1]);
                    mma16816(acc[mi][2 * p + 1], al4[mi], bh_t[2], bh_t[3]);
                }
            }
        }
    }

    // Epilogue
#pragma unroll
    for (int mi = 0; mi < 2; mi++) {
#pragma unroll
        for (int ni = 0; ni < 8; ni++) {
            int row0 = bm + wm + 16 * mi + g;
            int col = bn + wn + 8 * ni + 2 * tig;
            float v0 = acc[mi][ni][0] * scale, v1 = acc[mi][ni][1] * scale;
            float v2 = acc[mi][ni][2] * scale, v3 = acc[mi][ni][3] * scale;
            if (SPLIT_OUT) {
                uint32_t h, l;
                split_pack(v0, v1, h, l);
                *(uint32_t*)(Ch + (size_t)row0 * DD + col) = h;
                *(uint32_t*)(Cl + (size_t)row0 * DD + col) = l;
                split_pack(v2, v3, h, l);
                *(uint32_t*)(Ch + (size_t)(row0 + 8) * DD + col) = h;
                *(uint32_t*)(Cl + (size_t)(row0 + 8) * DD + col) = l;
            } else {
                *(float2*)(Cf + (size_t)row0 * DD + col) = make_float2(v0, v1);
                *(float2*)(Cf + (size_t)(row0 + 8) * DD + col) = make_float2(v2, v3);
            }
        }
    }
}

// ---------------------------------------------------------------------------
// Flash attention — EXACT R7 version (165.9us): static softmax, 3-stage KV
// ring, 1 barrier/tile, prefetch after S-block.
// ---------------------------------------------------------------------------
#define AT_ASZ (64 * 72 * 2)     // 9216 per array
#define AT_STAGE (4 * AT_ASZ)    // 36864
#define ATTN_SMEM (3 * AT_STAGE) // 110592

__global__ __launch_bounds__(128, 2) void attn_mma(
    const __nv_bfloat16* __restrict__ qh, const __nv_bfloat16* __restrict__ ql,
    const __nv_bfloat16* __restrict__ kh, const __nv_bfloat16* __restrict__ kl,
    const __nv_bfloat16* __restrict__ vh, const __nv_bfloat16* __restrict__ vl,
    __nv_bfloat16* __restrict__ oh, __nv_bfloat16* __restrict__ ol) {
    extern __shared__ char smc[];
    const uint32_t smb = smem_u32(smc);
    const int tid = threadIdx.x, lane = tid & 31, wid = tid >> 5;
    const int qt = (int)(gridDim.x - 1 - blockIdx.x);   // heavy tiles first
    const int h = blockIdx.y, b = blockIdx.z;
    const int qbase = qt * 64;
    const int g = lane >> 2, tig = lane & 3;
    const int wrow = 16 * wid;

    {
        const int qa = tid >> 6;
        const __nv_bfloat16* gq = qa ? ql : qh;
        uint32_t sbase = smb + qa * AT_ASZ;
        int t64 = tid & 63;
#pragma unroll
        for (int i = 0; i < 8; i++) {
            int id = i * 64 + t64;
            int row = id >> 3, ch = (id & 7) * 8;
            cpa16(sbase + (uint32_t)(row * 72 + ch) * 2,
                  gq + (size_t)(b * LL + qbase + row) * DD + h * HD + ch);
        }
    }
    CP_COMMIT();
    cp_wait<0>();
    __syncthreads();

    uint32_t qfh[4][4], qfl[4][4];
#pragma unroll
    for (int j = 0; j < 4; j++) {
        uint32_t off = (uint32_t)(((wrow + (lane & 15)) * 72 +
                                   16 * j + ((lane >> 4) << 3)) * 2);
        ldsm_x4(qfh[j], smb + off);
        ldsm_x4(qfl[j], smb + AT_ASZ + off);
    }
    __syncthreads();

    const int arr = wid;   // 0:Kh 1:Kl 2:Vh 3:Vl
    const __nv_bfloat16* gkv = (arr == 0) ? kh : (arr == 1) ? kl : (arr == 2) ? vh : vl;
    auto load_kv = [&](int st, int kb) {
        uint32_t sbase = smb + st * AT_STAGE + arr * AT_ASZ;
#pragma unroll
        for (int i = 0; i < 16; i++) {
            int id = i * 32 + lane;
            int row = id >> 3, ch = (id & 7) * 8;
            cpa16(sbase + (uint32_t)(row * 72 + ch) * 2,
                  gkv + (size_t)(b * LL + kb + row) * DD + h * HD + ch);
        }
    };

    const int nkt = qt + 1;
    load_kv(0, 0);
    CP_COMMIT();
    load_kv(1, 64);
    CP_COMMIT();

    float l0 = 0.0f, l1 = 0.0f;
    float o[8][4];
#pragma unroll
    for (int f = 0; f < 8; f++)
#pragma unroll
        for (int r = 0; r < 4; r++) o[f][r] = 0.0f;

    for (int kt = 0; kt < nkt; kt++) {
        cp_wait<1>();
        __syncthreads();

        const int kb = kt * 64;
        const int st = kt % 3;
        const uint32_t sKh = smb + st * AT_STAGE;
        const uint32_t sKl = sKh + AT_ASZ;
        const uint32_t sVh = sKh + 2 * AT_ASZ;
        const uint32_t sVl = sKh + 3 * AT_ASZ;

        float sf[8][4];
#pragma unroll
        for (int f = 0; f < 8; f++)
#pragma unroll
            for (int r = 0; r < 4; r++) sf[f][r] = 0.0f;

#pragma unroll
        for (int jj = 0; jj < 4; jj++) {
#pragma unroll
            for (int p = 0; p < 4; p++) {
                uint32_t off = (uint32_t)(((16 * p + ((lane >> 4) << 3) + (lane & 7)) * 72 +
                                           16 * jj + ((lane >> 3) & 1) * 8) * 2);
                uint32_t th[4], tl[4];
                ldsm_x4(th, sKh + off);
                ldsm_x4(tl, sKl + off);
                mma16816(sf[2 * p],     qfh[jj], th[0], th[1]);
                mma16816(sf[2 * p + 1], qfh[jj], th[2], th[3]);
                mma16816(sf[2 * p],     qfh[jj], tl[0], tl[1]);
                mma16816(sf[2 * p + 1], qfh[jj], tl[2], tl[3]);
                mma16816(sf[2 * p],     qfl[jj], th[0], th[1]);
                mma16816(sf[2 * p + 1], qfl[jj], th[2], th[3]);
            }
        }

        if (kt + 2 < nkt) load_kv((kt + 2) % 3, (kt + 2) * 64);
        CP_COMMIT();

        const int row0 = qbase + wrow + g, row1 = row0 + 8;
        if (kb + 63 > qbase + wrow) {
#pragma unroll
            for (int f = 0; f < 8; f++) {
                int col = kb + 8 * f + 2 * tig;
                if (col > row0) sf[f][0] = -1e30f;
                if (col + 1 > row0) sf[f][1] = -1e30f;
                if (col > row1) sf[f][2] = -1e30f;
                if (col + 1 > row1) sf[f][3] = -1e30f;
            }
        }

#pragma unroll
        for (int f = 0; f < 8; f++) {
            sf[f][0] = __expf(sf[f][0]);
            sf[f][1] = __expf(sf[f][1]);
            sf[f][2] = __expf(sf[f][2]);
            sf[f][3] = __expf(sf[f][3]);
            l0 += sf[f][0] + sf[f][1];
            l1 += sf[f][2] + sf[f][3];
        }

#pragma unroll
        for (int j = 0; j < 4; j++) {
            uint32_t pA_h[4], pA_l[4];
            split_pack(sf[2 * j][0], sf[2 * j][1], pA_h[0], pA_l[0]);
            split_pack(sf[2 * j][2], sf[2 * j][3], pA_h[1], pA_l[1]);
            split_pack(sf[2 * j + 1][0], sf[2 * j + 1][1], pA_h[2], pA_l[2]);
            split_pack(sf[2 * j + 1][2], sf[2 * j + 1][3], pA_h[3], pA_l[3]);
#pragma unroll
            for (int p = 0; p < 4; p++) {
                uint32_t off = (uint32_t)(((16 * j + ((lane >> 3) & 1) * 8 + (lane & 7)) * 72 +
                                           16 * p + (lane >> 4) * 8) * 2);
                uint32_t th[4], tl[4];
                ldsm_x4_t(th, sVh + off);
                ldsm_x4_t(tl, sVl + off);
                mma16816(o[2 * p],     pA_h, th[0], th[1]);
                mma16816(o[2 * p + 1], pA_h, th[2], th[3]);
                mma16816(o[2 * p],     pA_h, tl[0], tl[1]);
                mma16816(o[2 * p + 1], pA_h, tl[2], tl[3]);
                mma16816(o[2 * p],     pA_l, th[0], th[1]);
                mma16816(o[2 * p + 1], pA_l, th[2], th[3]);
            }
        }
    }

    l0 += __shfl_xor_sync(0xffffffffu, l0, 1);
    l0 += __shfl_xor_sync(0xffffffffu, l0, 2);
    l1 += __shfl_xor_sync(0xffffffffu, l1, 1);
    l1 += __shfl_xor_sync(0xffffffffu, l1, 2);
    const float i0 = 1.0f / l0, i1 = 1.0f / l1;
    const size_t grow0 = (size_t)(b * LL + qbase + wrow + g);
    const size_t grow1 = grow0 + 8;
#pragma unroll
    for (int f = 0; f < 8; f++) {
        int col = h * HD + 8 * f + 2 * tig;
        uint32_t hi, lo;
        split_pack(o[f][0] * i0, o[f][1] * i0, hi, lo);
        *(uint32_t*)(oh + grow0 * DD + col) = hi;
        *(uint32_t*)(ol + grow0 * DD + col) = lo;
        split_pack(o[f][2] * i1, o[f][3] * i1, hi, lo);
        *(uint32_t*)(oh + grow1 * DD + col) = hi;
        *(uint32_t*)(ol + grow1 * DD + col) = lo;
    }
}

// ---------------------------------------------------------------------------
// Conversions
// ---------------------------------------------------------------------------
__global__ __launch_bounds__(256) void conv_split(const float* __restrict__ x,
                                                  __nv_bfloat16* __restrict__ xh,
                                                  __nv_bfloat16* __restrict__ xl) {
    int i = (blockIdx.x * 256 + threadIdx.x) * 4;
    float4 v = *(const float4*)(x + i);
    float f[4] = {v.x, v.y, v.z, v.w};
    __nv_bfloat16 hh[4], ll[4];
#pragma unroll
    for (int j = 0; j < 4; j++) {
        hh[j] = __float2bfloat16(f[j]);
        ll[j] = __float2bfloat16(f[j] - __bfloat162float(hh[j]));
    }
    *(uint2*)(xh + i) = *(uint2*)hh;
    *(uint2*)(xl + i) = *(uint2*)ll;
}

__global__ __launch_bounds__(256) void conv_w4(const float* __restrict__ W0,
                                               const float* __restrict__ W1,
                                               const float* __restrict__ W2,
                                               const float* __restrict__ W3,
                                               __nv_bfloat16* __restrict__ Th,
                                               __nv_bfloat16* __restrict__ Tl) {
    __shared__ float t[32][33];
    const int tx = threadIdx.x, ty = threadIdx.y;  // 32 x 8
    const int n0 = blockIdx.x * 32, k0 = blockIdx.y * 32;
    const int z = blockIdx.z;
    const float* W = (z == 0) ? W0 : (z == 1) ? W1 : (z == 2) ? W2 : W3;
    __nv_bfloat16* th = Th + (size_t)z * DD * DD;
    __nv_bfloat16* tl = Tl + (size_t)z * DD * DD;
#pragma unroll
    for (int j = 0; j < 32; j += 8)
        t[ty + j][tx] = W[(size_t)(k0 + ty + j) * DD + n0 + tx];
    __syncthreads();
#pragma unroll
    for (int j = 0; j < 32; j += 8) {
        float v = t[tx][ty + j];
        __nv_bfloat16 hh = __float2bfloat16(v);
        __nv_bfloat16 ll = __float2bfloat16(v - __bfloat162float(hh));
        th[(size_t)(n0 + ty + j) * DD + k0 + tx] = hh;
        tl[(size_t)(n0 + ty + j) * DD + k0 + tx] = ll;
    }
}

// ---------------------------------------------------------------------------
// Launch
// ---------------------------------------------------------------------------
extern "C" void kernel_launch(void* const* d_in, const int* in_sizes, int n_in,
                              void* d_out, int out_size) {
    const float* x  = (const float*)d_in[0];
    const float* Wk = (const float*)d_in[1];
    const float* Wq = (const float*)d_in[2];
    const float* Wv = (const float*)d_in[3];
    const float* Wo = (const float*)d_in[4];
    float* out = (float*)d_out;

    void *p;
#define GETP(sym, var) cudaGetSymbolAddress(&p, sym); __nv_bfloat16* var = (__nv_bfloat16*)p;
    GETP(g_xh, xh) GETP(g_xl, xl)
    GETP(g_qh, qh) GETP(g_ql, ql)
    GETP(g_kh, kh) GETP(g_kl, kl)
    GETP(g_vh, vh) GETP(g_vl, vl)
    GETP(g_ah, ah) GETP(g_al, al)
    GETP(g_wh, wh) GETP(g_wl, wl)
#undef GETP

    static bool attrs_set = false;
    if (!attrs_set) {
        cudaFuncSetAttribute(gemm_mma<true>, cudaFuncAttributeMaxDynamicSharedMemorySize, GEMM_SMEM);
        cudaFuncSetAttribute(gemm_mma<false>, cudaFuncAttributeMaxDynamicSharedMemorySize, GEMM_SMEM);
        cudaFuncSetAttribute(attn_mma, cudaFuncAttributeMaxDynamicSharedMemorySize, ATTN_SMEM);
        attrs_set = true;
    }

    // 1. conversions (weight order: 0=Wq, 1=Wk, 2=Wv, 3=Wo)
    conv_split<<<MM * DD / (256 * 4), 256>>>(x, xh, xl);
    dim3 wgrid(DD / 32, DD / 32, 4);
    dim3 wblk(32, 8);
    conv_w4<<<wgrid, wblk>>>(Wq, Wk, Wv, Wo, wh, wl);

    // 2. fused QKV projections (z: 0=Q pre-scaled 0.125, 1=K, 2=V)
    dim3 ggrid(DD / 128, MM / 128, 3);   // (8, 32, 3) = 768 CTAs
    gemm_mma<true><<<ggrid, 256, GEMM_SMEM>>>(xh, xl, wh, wl,
                                              qh, ql, kh, kl, vh, vl, nullptr);

    // 3. attention (64-row q tiles, static softmax, 3-stage ring — R7 exact)
    dim3 agrid(LL / 64, HH, BB);  // (32, 16, 2)
    attn_mma<<<agrid, 128, ATTN_SMEM>>>(qh, ql, kh, kl, vh, vl, ah, al);

    // 4. output projection (fp32 out) — 256 CTAs = single wave
    dim3 ogrid(DD / 128, MM / 128, 1);
    gemm_mma<false><<<ogrid, 256, GEMM_SMEM>>>(ah, al,
                                               wh + 3 * (size_t)DD * DD, wl + 3 * (size_t)DD * DD,
                                               nullptr, nullptr, nullptr, nullptr, nullptr, nullptr,
                                               out);
}

// round 13
// speedup vs baseline: 1.0380x; 1.0380x over previous
#include <cuda_runtime.h>
#include <cuda_bf16.h>
#include <cstdint>

// Problem constants
#define BB 2
#define LL 2048
#define DD 1024
#define HH 16
#define HD 64
#define MM (BB * LL)   // 4096 rows

// ---------------------------------------------------------------------------
// Scratch (device globals; no allocations allowed). All split-bf16 pairs.
// ---------------------------------------------------------------------------
__device__ __align__(1024) __nv_bfloat16 g_xh[MM * DD], g_xl[MM * DD];
__device__ __align__(1024) __nv_bfloat16 g_qh[MM * DD], g_ql[MM * DD];
__device__ __align__(1024) __nv_bfloat16 g_kh[MM * DD], g_kl[MM * DD];
__device__ __align__(1024) __nv_bfloat16 g_vh[MM * DD], g_vl[MM * DD];
__device__ __align__(1024) __nv_bfloat16 g_ah[MM * DD], g_al[MM * DD];
__device__ __align__(1024) __nv_bfloat16 g_wh[4][DD * DD], g_wl[4][DD * DD];

// ---------------------------------------------------------------------------
// Helpers (base sm_103-safe: mma.sync / ldmatrix / cp.async only)
// ---------------------------------------------------------------------------
__device__ __forceinline__ uint32_t smem_u32(const void* p) {
    uint32_t a;
    asm("{ .reg .u64 t; cvta.to.shared.u64 t, %1; cvt.u32.u64 %0, t; }" : "=r"(a) : "l"(p));
    return a;
}
__device__ __forceinline__ void cpa16(uint32_t dst, const void* src) {
    asm volatile("cp.async.cg.shared.global [%0], [%1], 16;" :: "r"(dst), "l"(src));
}
#define CP_COMMIT() asm volatile("cp.async.commit_group;" ::: "memory")
template <int N>
__device__ __forceinline__ void cp_wait() {
    asm volatile("cp.async.wait_group %0;" :: "n"(N) : "memory");
}
__device__ __forceinline__ void ldsm_x4(uint32_t (&r)[4], uint32_t addr) {
    asm volatile("ldmatrix.sync.aligned.m8n8.x4.shared.b16 {%0,%1,%2,%3}, [%4];"
                 : "=r"(r[0]), "=r"(r[1]), "=r"(r[2]), "=r"(r[3]) : "r"(addr));
}
__device__ __forceinline__ void ldsm_x4_t(uint32_t (&r)[4], uint32_t addr) {
    asm volatile("ldmatrix.sync.aligned.m8n8.x4.trans.shared.b16 {%0,%1,%2,%3}, [%4];"
                 : "=r"(r[0]), "=r"(r[1]), "=r"(r[2]), "=r"(r[3]) : "r"(addr));
}
__device__ __forceinline__ void mma16816(float (&d)[4], const uint32_t (&a)[4],
                                         uint32_t b0, uint32_t b1) {
    asm volatile(
        "mma.sync.aligned.m16n8k16.row.col.f32.bf16.bf16.f32 "
        "{%0,%1,%2,%3}, {%4,%5,%6,%7}, {%8,%9}, {%0,%1,%2,%3};"
        : "+f"(d[0]), "+f"(d[1]), "+f"(d[2]), "+f"(d[3])
        : "r"(a[0]), "r"(a[1]), "r"(a[2]), "r"(a[3]), "r"(b0), "r"(b1));
}
__device__ __forceinline__ uint32_t pack2(float lo, float hi) {
    __nv_bfloat162 t = __floats2bfloat162_rn(lo, hi);
    return *(uint32_t*)&t;
}
__device__ __forceinline__ void split_pack(float v0, float v1, uint32_t& h, uint32_t& l) {
    __nv_bfloat16 h0 = __float2bfloat16(v0), h1 = __float2bfloat16(v1);
    float l0 = v0 - __bfloat162float(h0), l1 = v1 - __bfloat162float(h1);
    __nv_bfloat162 hp; hp.x = h0; hp.y = h1;
    h = *(uint32_t*)&hp;
    l = pack2(l0, l1);
}

// ---------------------------------------------------------------------------
// Split-bf16 mma.sync GEMM — R10 WINNER, exact revert.
// CTA tile 128x64, BK=64, two-stage double buffer, one barrier per chunk.
// 128B rows with full SW128 swizzle. 2 CTAs/SM.
// ---------------------------------------------------------------------------
#define GA_SZ (128 * 64 * 2)        // 16384 B per A array
#define GB_SZ (64 * 64 * 2)         // 8192 B per B array
#define GK_STAGE (2 * GA_SZ + 2 * GB_SZ)  // 49152 B
#define GEMM_SMEM (2 * GK_STAGE)    // 98304 B

__device__ __forceinline__ uint32_t gsw128(int row, int unit) {  // 128B-row SW128
    return (uint32_t)(row * 128 + ((unit ^ (row & 7)) << 4));
}

template <bool SPLIT_OUT>
__global__ __launch_bounds__(256, 2) void gemm_mma(
    const __nv_bfloat16* __restrict__ Ah, const __nv_bfloat16* __restrict__ Al,
    const __nv_bfloat16* __restrict__ Bh0, const __nv_bfloat16* __restrict__ Bl0,
    __nv_bfloat16* __restrict__ Ch0, __nv_bfloat16* __restrict__ Cl0,
    __nv_bfloat16* __restrict__ Ch1, __nv_bfloat16* __restrict__ Cl1,
    __nv_bfloat16* __restrict__ Ch2, __nv_bfloat16* __restrict__ Cl2,
    float* __restrict__ Cf) {
    extern __shared__ char smc[];
    const uint32_t smb = smem_u32(smc);
    const int tid = threadIdx.x, lane = tid & 31, wid = tid >> 5;
    const int wm = (wid & 3) * 32, wn = (wid >> 2) * 32;
    const int bm = blockIdx.y * 128, bn = blockIdx.x * 64;
    const int z = blockIdx.z;
    const int g = lane >> 2, tig = lane & 3;

    const __nv_bfloat16* Bh = Bh0 + (size_t)z * DD * DD;
    const __nv_bfloat16* Bl = Bl0 + (size_t)z * DD * DD;
    __nv_bfloat16* Ch = (z == 0) ? Ch0 : (z == 1) ? Ch1 : Ch2;
    __nv_bfloat16* Cl = (z == 0) ? Cl0 : (z == 1) ? Cl1 : Cl2;
    const float scale = (SPLIT_OUT && z == 0) ? 0.125f : 1.0f;

    float acc[2][4][4];
#pragma unroll
    for (int a = 0; a < 2; a++)
#pragma unroll
        for (int b = 0; b < 4; b++)
#pragma unroll
            for (int c = 0; c < 4; c++) acc[a][b][c] = 0.0f;

    auto load_stage = [&](int s, int c) {
        const uint32_t sb = smb + s * GK_STAGE;
#pragma unroll
        for (int i = 0; i < 12; i++) {
            int u = tid + i * 256;
            if (u < 2048) {
                int arr = u >> 10;
                int w = u & 1023;
                int row = w >> 3, un = w & 7;
                const __nv_bfloat16* src = (arr ? Al : Ah) + (size_t)(bm + row) * DD + c * 64 + un * 8;
                cpa16(sb + arr * GA_SZ + gsw128(row, un), src);
            } else {
                int u2 = u - 2048;
                int arr = u2 >> 9;
                int w = u2 & 511;
                int row = w >> 3, un = w & 7;
                const __nv_bfloat16* src = (arr ? Bl : Bh) + (size_t)(bn + row) * DD + c * 64 + un * 8;
                cpa16(sb + 2 * GA_SZ + arr * GB_SZ + gsw128(row, un), src);
            }
        }
    };

    load_stage(0, 0);
    CP_COMMIT();

    for (int c = 0; c < 16; c++) {
        cp_wait<0>();
        __syncthreads();
        if (c + 1 < 16) load_stage((c + 1) & 1, c + 1);
        CP_COMMIT();

        const uint32_t sA_h = smb + (c & 1) * GK_STAGE;
        const uint32_t sA_l = sA_h + GA_SZ;
        const uint32_t sB_h = sA_h + 2 * GA_SZ;
        const uint32_t sB_l = sB_h + GB_SZ;
#pragma unroll
        for (int j = 0; j < 4; j++) {
            uint32_t ah4[2][4], al4[2][4];
#pragma unroll
            for (int mi = 0; mi < 2; mi++) {
                int row = wm + 16 * mi + (lane & 15);
                int un = 2 * j + (lane >> 4);
                uint32_t off = gsw128(row, un);
                ldsm_x4(ah4[mi], sA_h + off);
                ldsm_x4(al4[mi], sA_l + off);
            }
            uint32_t bh[4][2], bl[4][2];
#pragma unroll
            for (int p = 0; p < 2; p++) {
                int row = wn + 16 * p + ((lane >> 4) << 3) + (lane & 7);
                int un = 2 * j + ((lane >> 3) & 1);
                uint32_t off = gsw128(row, un);
                uint32_t t[4];
                ldsm_x4(t, sB_h + off);
                bh[2 * p][0] = t[0]; bh[2 * p][1] = t[1];
                bh[2 * p + 1][0] = t[2]; bh[2 * p + 1][1] = t[3];
                ldsm_x4(t, sB_l + off);
                bl[2 * p][0] = t[0]; bl[2 * p][1] = t[1];
                bl[2 * p + 1][0] = t[2]; bl[2 * p + 1][1] = t[3];
            }
#pragma unroll
            for (int t = 0; t < 3; t++)
#pragma unroll
                for (int mi = 0; mi < 2; mi++)
#pragma unroll
                    for (int ni = 0; ni < 4; ni++) {
                        const uint32_t (&af)[4] = (t == 2) ? al4[mi] : ah4[mi];
                        const uint32_t b0 = (t == 1) ? bl[ni][0] : bh[ni][0];
                        const uint32_t b1 = (t == 1) ? bl[ni][1] : bh[ni][1];
                        mma16816(acc[mi][ni], af, b0, b1);
                    }
        }
    }

    // Epilogue
#pragma unroll
    for (int mi = 0; mi < 2; mi++) {
#pragma unroll
        for (int ni = 0; ni < 4; ni++) {
            int row0 = bm + wm + 16 * mi + g;
            int col = bn + wn + 8 * ni + 2 * tig;
            float v0 = acc[mi][ni][0] * scale, v1 = acc[mi][ni][1] * scale;
            float v2 = acc[mi][ni][2] * scale, v3 = acc[mi][ni][3] * scale;
            if (SPLIT_OUT) {
                uint32_t h, l;
                split_pack(v0, v1, h, l);
                *(uint32_t*)(Ch + (size_t)row0 * DD + col) = h;
                *(uint32_t*)(Cl + (size_t)row0 * DD + col) = l;
                split_pack(v2, v3, h, l);
                *(uint32_t*)(Ch + (size_t)(row0 + 8) * DD + col) = h;
                *(uint32_t*)(Cl + (size_t)(row0 + 8) * DD + col) = l;
            } else {
                *(float2*)(Cf + (size_t)row0 * DD + col) = make_float2(v0, v1);
                *(float2*)(Cf + (size_t)(row0 + 8) * DD + col) = make_float2(v2, v3);
            }
        }
    }
}

// ---------------------------------------------------------------------------
// Flash attention — R7 protocol with TWO-stage KV ring (73.7KB) and
// __launch_bounds__(128,3) for 3 CTAs/SM (12 warps). Single barrier/tile:
// barrier at tile kt proves reads of slot (kt-1)&1 done -> safe to write
// slot (kt+1)&1 after it. cp_wait<0> before barrier publishes tile kt.
// ---------------------------------------------------------------------------
#define AT_ASZ (64 * 72 * 2)     // 9216 per array
#define AT_STAGE (4 * AT_ASZ)    // 36864
#define ATTN_SMEM (2 * AT_STAGE) // 73728

__global__ __launch_bounds__(128, 3) void attn_mma(
    const __nv_bfloat16* __restrict__ qh, const __nv_bfloat16* __restrict__ ql,
    const __nv_bfloat16* __restrict__ kh, const __nv_bfloat16* __restrict__ kl,
    const __nv_bfloat16* __restrict__ vh, const __nv_bfloat16* __restrict__ vl,
    __nv_bfloat16* __restrict__ oh, __nv_bfloat16* __restrict__ ol) {
    extern __shared__ char smc[];
    const uint32_t smb = smem_u32(smc);
    const int tid = threadIdx.x, lane = tid & 31, wid = tid >> 5;
    const int qt = (int)(gridDim.x - 1 - blockIdx.x);   // heavy tiles first
    const int h = blockIdx.y, b = blockIdx.z;
    const int qbase = qt * 64;
    const int g = lane >> 2, tig = lane & 3;
    const int wrow = 16 * wid;

    // Stage Q through slot 0 (arrays 0,1), read fragments, then reuse for KV.
    {
        const int qa = tid >> 6;
        const __nv_bfloat16* gq = qa ? ql : qh;
        uint32_t sbase = smb + qa * AT_ASZ;
        int t64 = tid & 63;
#pragma unroll
        for (int i = 0; i < 8; i++) {
            int id = i * 64 + t64;
            int row = id >> 3, ch = (id & 7) * 8;
            cpa16(sbase + (uint32_t)(row * 72 + ch) * 2,
                  gq + (size_t)(b * LL + qbase + row) * DD + h * HD + ch);
        }
    }
    CP_COMMIT();
    cp_wait<0>();
    __syncthreads();

    uint32_t qfh[4][4], qfl[4][4];
#pragma unroll
    for (int j = 0; j < 4; j++) {
        uint32_t off = (uint32_t)(((wrow + (lane & 15)) * 72 +
                                   16 * j + ((lane >> 4) << 3)) * 2);
        ldsm_x4(qfh[j], smb + off);
        ldsm_x4(qfl[j], smb + AT_ASZ + off);
    }
    __syncthreads();   // all warps done reading Q before KV overwrites slot 0

    const int arr = wid;   // 0:Kh 1:Kl 2:Vh 3:Vl
    const __nv_bfloat16* gkv = (arr == 0) ? kh : (arr == 1) ? kl : (arr == 2) ? vh : vl;
    auto load_kv = [&](int st, int kb) {
        uint32_t sbase = smb + st * AT_STAGE + arr * AT_ASZ;
#pragma unroll
        for (int i = 0; i < 16; i++) {
            int id = i * 32 + lane;
            int row = id >> 3, ch = (id & 7) * 8;
            cpa16(sbase + (uint32_t)(row * 72 + ch) * 2,
                  gkv + (size_t)(b * LL + kb + row) * DD + h * HD + ch);
        }
    };

    const int nkt = qt + 1;
    load_kv(0, 0);
    CP_COMMIT();

    float l0 = 0.0f, l1 = 0.0f;
    float o[8][4];
#pragma unroll
    for (int f = 0; f < 8; f++)
#pragma unroll
        for (int r = 0; r < 4; r++) o[f][r] = 0.0f;

    for (int kt = 0; kt < nkt; kt++) {
        cp_wait<0>();      // tile kt's loads complete
        __syncthreads();   // publish; also proves reads of slot (kt+1)&1 done

        // Prefetch next tile into the freed slot (required for overlap at depth 1).
        if (kt + 1 < nkt) load_kv((kt + 1) & 1, (kt + 1) * 64);
        CP_COMMIT();

        const int kb = kt * 64;
        const uint32_t sKh = smb + (kt & 1) * AT_STAGE;
        const uint32_t sKl = sKh + AT_ASZ;
        const uint32_t sVh = sKh + 2 * AT_ASZ;
        const uint32_t sVl = sKh + 3 * AT_ASZ;

        float sf[8][4];
#pragma unroll
        for (int f = 0; f < 8; f++)
#pragma unroll
            for (int r = 0; r < 4; r++) sf[f][r] = 0.0f;

        // S = Qh*Kh + Qh*Kl + Ql*Kh
#pragma unroll
        for (int jj = 0; jj < 4; jj++) {
#pragma unroll
            for (int p = 0; p < 4; p++) {
                uint32_t off = (uint32_t)(((16 * p + ((lane >> 4) << 3) + (lane & 7)) * 72 +
                                           16 * jj + ((lane >> 3) & 1) * 8) * 2);
                uint32_t th[4], tl[4];
                ldsm_x4(th, sKh + off);
                ldsm_x4(tl, sKl + off);
                mma16816(sf[2 * p],     qfh[jj], th[0], th[1]);
                mma16816(sf[2 * p + 1], qfh[jj], th[2], th[3]);
                mma16816(sf[2 * p],     qfh[jj], tl[0], tl[1]);
                mma16816(sf[2 * p + 1], qfh[jj], tl[2], tl[3]);
                mma16816(sf[2 * p],     qfl[jj], th[0], th[1]);
                mma16816(sf[2 * p + 1], qfl[jj], th[2], th[3]);
            }
        }

        const int row0 = qbase + wrow + g, row1 = row0 + 8;
        if (kb + 63 > qbase + wrow) {  // diagonal tile: causal mask
#pragma unroll
            for (int f = 0; f < 8; f++) {
                int col = kb + 8 * f + 2 * tig;
                if (col > row0) sf[f][0] = -1e30f;
                if (col + 1 > row0) sf[f][1] = -1e30f;
                if (col > row1) sf[f][2] = -1e30f;
                if (col + 1 > row1) sf[f][3] = -1e30f;
            }
        }

        // Static softmax
#pragma unroll
        for (int f = 0; f < 8; f++) {
            sf[f][0] = __expf(sf[f][0]);
            sf[f][1] = __expf(sf[f][1]);
            sf[f][2] = __expf(sf[f][2]);
            sf[f][3] = __expf(sf[f][3]);
            l0 += sf[f][0] + sf[f][1];
            l1 += sf[f][2] + sf[f][3];
        }

        // O += Ph*Vh + Ph*Vl + Pl*Vh
#pragma unroll
        for (int j = 0; j < 4; j++) {
            uint32_t pA_h[4], pA_l[4];
            split_pack(sf[2 * j][0], sf[2 * j][1], pA_h[0], pA_l[0]);
            split_pack(sf[2 * j][2], sf[2 * j][3], pA_h[1], pA_l[1]);
            split_pack(sf[2 * j + 1][0], sf[2 * j + 1][1], pA_h[2], pA_l[2]);
            split_pack(sf[2 * j + 1][2], sf[2 * j + 1][3], pA_h[3], pA_l[3]);
#pragma unroll
            for (int p = 0; p < 4; p++) {
                uint32_t off = (uint32_t)(((16 * j + ((lane >> 3) & 1) * 8 + (lane & 7)) * 72 +
                                           16 * p + (lane >> 4) * 8) * 2);
                uint32_t th[4], tl[4];
                ldsm_x4_t(th, sVh + off);
                ldsm_x4_t(tl, sVl + off);
                mma16816(o[2 * p],     pA_h, th[0], th[1]);
                mma16816(o[2 * p + 1], pA_h, th[2], th[3]);
                mma16816(o[2 * p],     pA_h, tl[0], tl[1]);
                mma16816(o[2 * p + 1], pA_h, tl[2], tl[3]);
                mma16816(o[2 * p],     pA_l, th[0], th[1]);
                mma16816(o[2 * p + 1], pA_l, th[2], th[3]);
            }
        }
        // NO tail barrier: next iteration's top barrier provides the ordering.
    }

    l0 += __shfl_xor_sync(0xffffffffu, l0, 1);
    l0 += __shfl_xor_sync(0xffffffffu, l0, 2);
    l1 += __shfl_xor_sync(0xffffffffu, l1, 1);
    l1 += __shfl_xor_sync(0xffffffffu, l1, 2);
    const float i0 = 1.0f / l0, i1 = 1.0f / l1;
    const size_t grow0 = (size_t)(b * LL + qbase + wrow + g);
    const size_t grow1 = grow0 + 8;
#pragma unroll
    for (int f = 0; f < 8; f++) {
        int col = h * HD + 8 * f + 2 * tig;
        uint32_t hi, lo;
        split_pack(o[f][0] * i0, o[f][1] * i0, hi, lo);
        *(uint32_t*)(oh + grow0 * DD + col) = hi;
        *(uint32_t*)(ol + grow0 * DD + col) = lo;
        split_pack(o[f][2] * i1, o[f][3] * i1, hi, lo);
        *(uint32_t*)(oh + grow1 * DD + col) = hi;
        *(uint32_t*)(ol + grow1 * DD + col) = lo;
    }
}

// ---------------------------------------------------------------------------
// Conversions
// ---------------------------------------------------------------------------
__global__ __launch_bounds__(256) void conv_split(const float* __restrict__ x,
                                                  __nv_bfloat16* __restrict__ xh,
                                                  __nv_bfloat16* __restrict__ xl) {
    int i = (blockIdx.x * 256 + threadIdx.x) * 4;
    float4 v = *(const float4*)(x + i);
    float f[4] = {v.x, v.y, v.z, v.w};
    __nv_bfloat16 hh[4], ll[4];
#pragma unroll
    for (int j = 0; j < 4; j++) {
        hh[j] = __float2bfloat16(f[j]);
        ll[j] = __float2bfloat16(f[j] - __bfloat162float(hh[j]));
    }
    *(uint2*)(xh + i) = *(uint2*)hh;
    *(uint2*)(xl + i) = *(uint2*)ll;
}

__global__ __launch_bounds__(256) void conv_w4(const float* __restrict__ W0,
                                               const float* __restrict__ W1,
                                               const float* __restrict__ W2,
                                               const float* __restrict__ W3,
                                               __nv_bfloat16* __restrict__ Th,
                                               __nv_bfloat16* __restrict__ Tl) {
    __shared__ float t[32][33];
    const int tx = threadIdx.x, ty = threadIdx.y;  // 32 x 8
    const int n0 = blockIdx.x * 32, k0 = blockIdx.y * 32;
    const int z = blockIdx.z;
    const float* W = (z == 0) ? W0 : (z == 1) ? W1 : (z == 2) ? W2 : W3;
    __nv_bfloat16* th = Th + (size_t)z * DD * DD;
    __nv_bfloat16* tl = Tl + (size_t)z * DD * DD;
#pragma unroll
    for (int j = 0; j < 32; j += 8)
        t[ty + j][tx] = W[(size_t)(k0 + ty + j) * DD + n0 + tx];
    __syncthreads();
#pragma unroll
    for (int j = 0; j < 32; j += 8) {
        float v = t[tx][ty + j];
        __nv_bfloat16 hh = __float2bfloat16(v);
        __nv_bfloat16 ll = __float2bfloat16(v - __bfloat162float(hh));
        th[(size_t)(n0 + ty + j) * DD + k0 + tx] = hh;
        tl[(size_t)(n0 + ty + j) * DD + k0 + tx] = ll;
    }
}

// ---------------------------------------------------------------------------
// Launch
// ---------------------------------------------------------------------------
extern "C" void kernel_launch(void* const* d_in, const int* in_sizes, int n_in,
                              void* d_out, int out_size) {
    const float* x  = (const float*)d_in[0];
    const float* Wk = (const float*)d_in[1];
    const float* Wq = (const float*)d_in[2];
    const float* Wv = (const float*)d_in[3];
    const float* Wo = (const float*)d_in[4];
    float* out = (float*)d_out;

    void *p;
#define GETP(sym, var) cudaGetSymbolAddress(&p, sym); __nv_bfloat16* var = (__nv_bfloat16*)p;
    GETP(g_xh, xh) GETP(g_xl, xl)
    GETP(g_qh, qh) GETP(g_ql, ql)
    GETP(g_kh, kh) GETP(g_kl, kl)
    GETP(g_vh, vh) GETP(g_vl, vl)
    GETP(g_ah, ah) GETP(g_al, al)
    GETP(g_wh, wh) GETP(g_wl, wl)
#undef GETP

    static bool attrs_set = false;
    if (!attrs_set) {
        cudaFuncSetAttribute(gemm_mma<true>, cudaFuncAttributeMaxDynamicSharedMemorySize, GEMM_SMEM);
        cudaFuncSetAttribute(gemm_mma<false>, cudaFuncAttributeMaxDynamicSharedMemorySize, GEMM_SMEM);
        cudaFuncSetAttribute(attn_mma, cudaFuncAttributeMaxDynamicSharedMemorySize, ATTN_SMEM);
        attrs_set = true;
    }

    // 1. conversions (weight order: 0=Wq, 1=Wk, 2=Wv, 3=Wo)
    conv_split<<<MM * DD / (256 * 4), 256>>>(x, xh, xl);
    dim3 wgrid(DD / 32, DD / 32, 4);
    dim3 wblk(32, 8);
    conv_w4<<<wgrid, wblk>>>(Wq, Wk, Wv, Wo, wh, wl);

    // 2. fused QKV projections (z: 0=Q pre-scaled 0.125, 1=K, 2=V)
    dim3 ggrid(DD / 64, MM / 128, 3);   // (16, 32, 3)
    gemm_mma<true><<<ggrid, 256, GEMM_SMEM>>>(xh, xl, wh, wl,
                                              qh, ql, kh, kl, vh, vl, nullptr);

    // 3. attention (64-row q tiles, static softmax, 2-stage ring, 3 CTAs/SM)
    dim3 agrid(LL / 64, HH, BB);  // (32, 16, 2)
    attn_mma<<<agrid, 128, ATTN_SMEM>>>(qh, ql, kh, kl, vh, vl, ah, al);

    // 4. output projection (fp32 out)
    dim3 ogrid(DD / 64, MM / 128, 1);
    gemm_mma<false><<<ogrid, 256, GEMM_SMEM>>>(ah, al,
                                               wh + 3 * (size_t)DD * DD, wl + 3 * (size_t)DD * DD,
                                               nullptr, nullptr, nullptr, nullptr, nullptr, nullptr,
                                               out);
}

// round 14
// speedup vs baseline: 1.0892x; 1.0493x over previous
#include <cuda_runtime.h>
#include <cuda_bf16.h>
#include <cstdint>

// Problem constants
#define BB 2
#define LL 2048
#define DD 1024
#define HH 16
#define HD 64
#define MM (BB * LL)   // 4096 rows

// ---------------------------------------------------------------------------
// Scratch (device globals; no allocations allowed). All split-bf16 pairs.
// ---------------------------------------------------------------------------
__device__ __align__(1024) __nv_bfloat16 g_xh[MM * DD], g_xl[MM * DD];
__device__ __align__(1024) __nv_bfloat16 g_qh[MM * DD], g_ql[MM * DD];
__device__ __align__(1024) __nv_bfloat16 g_kh[MM * DD], g_kl[MM * DD];
__device__ __align__(1024) __nv_bfloat16 g_vh[MM * DD], g_vl[MM * DD];
__device__ __align__(1024) __nv_bfloat16 g_ah[MM * DD], g_al[MM * DD];
__device__ __align__(1024) __nv_bfloat16 g_wh[4][DD * DD], g_wl[4][DD * DD];

// ---------------------------------------------------------------------------
// Helpers (base sm_103-safe: mma.sync / ldmatrix / cp.async only)
// ---------------------------------------------------------------------------
__device__ __forceinline__ uint32_t smem_u32(const void* p) {
    uint32_t a;
    asm("{ .reg .u64 t; cvta.to.shared.u64 t, %1; cvt.u32.u64 %0, t; }" : "=r"(a) : "l"(p));
    return a;
}
__device__ __forceinline__ void cpa16(uint32_t dst, const void* src) {
    asm volatile("cp.async.cg.shared.global [%0], [%1], 16;" :: "r"(dst), "l"(src));
}
#define CP_COMMIT() asm volatile("cp.async.commit_group;" ::: "memory")
template <int N>
__device__ __forceinline__ void cp_wait() {
    asm volatile("cp.async.wait_group %0;" :: "n"(N) : "memory");
}
__device__ __forceinline__ void ldsm_x4(uint32_t (&r)[4], uint32_t addr) {
    asm volatile("ldmatrix.sync.aligned.m8n8.x4.shared.b16 {%0,%1,%2,%3}, [%4];"
                 : "=r"(r[0]), "=r"(r[1]), "=r"(r[2]), "=r"(r[3]) : "r"(addr));
}
__device__ __forceinline__ void ldsm_x4_t(uint32_t (&r)[4], uint32_t addr) {
    asm volatile("ldmatrix.sync.aligned.m8n8.x4.trans.shared.b16 {%0,%1,%2,%3}, [%4];"
                 : "=r"(r[0]), "=r"(r[1]), "=r"(r[2]), "=r"(r[3]) : "r"(addr));
}
__device__ __forceinline__ void mma16816(float (&d)[4], const uint32_t (&a)[4],
                                         uint32_t b0, uint32_t b1) {
    asm volatile(
        "mma.sync.aligned.m16n8k16.row.col.f32.bf16.bf16.f32 "
        "{%0,%1,%2,%3}, {%4,%5,%6,%7}, {%8,%9}, {%0,%1,%2,%3};"
        : "+f"(d[0]), "+f"(d[1]), "+f"(d[2]), "+f"(d[3])
        : "r"(a[0]), "r"(a[1]), "r"(a[2]), "r"(a[3]), "r"(b0), "r"(b1));
}
__device__ __forceinline__ uint32_t pack2(float lo, float hi) {
    __nv_bfloat162 t = __floats2bfloat162_rn(lo, hi);
    return *(uint32_t*)&t;
}
__device__ __forceinline__ void split_pack(float v0, float v1, uint32_t& h, uint32_t& l) {
    __nv_bfloat16 h0 = __float2bfloat16(v0), h1 = __float2bfloat16(v1);
    float l0 = v0 - __bfloat162float(h0), l1 = v1 - __bfloat162float(h1);
    __nv_bfloat162 hp; hp.x = h0; hp.y = h1;
    h = *(uint32_t*)&hp;
    l = pack2(l0, l1);
}

// ---------------------------------------------------------------------------
// Split-bf16 mma.sync GEMM — R10 WINNER, unchanged.
// CTA tile 128x64, BK=64, two-stage double buffer, one barrier per chunk.
// ---------------------------------------------------------------------------
#define GA_SZ (128 * 64 * 2)        // 16384 B per A array
#define GB_SZ (64 * 64 * 2)         // 8192 B per B array
#define GK_STAGE (2 * GA_SZ + 2 * GB_SZ)  // 49152 B
#define GEMM_SMEM (2 * GK_STAGE)    // 98304 B

__device__ __forceinline__ uint32_t gsw128(int row, int unit) {  // 128B-row SW128
    return (uint32_t)(row * 128 + ((unit ^ (row & 7)) << 4));
}

template <bool SPLIT_OUT>
__global__ __launch_bounds__(256, 2) void gemm_mma(
    const __nv_bfloat16* __restrict__ Ah, const __nv_bfloat16* __restrict__ Al,
    const __nv_bfloat16* __restrict__ Bh0, const __nv_bfloat16* __restrict__ Bl0,
    __nv_bfloat16* __restrict__ Ch0, __nv_bfloat16* __restrict__ Cl0,
    __nv_bfloat16* __restrict__ Ch1, __nv_bfloat16* __restrict__ Cl1,
    __nv_bfloat16* __restrict__ Ch2, __nv_bfloat16* __restrict__ Cl2,
    float* __restrict__ Cf) {
    extern __shared__ char smc[];
    const uint32_t smb = smem_u32(smc);
    const int tid = threadIdx.x, lane = tid & 31, wid = tid >> 5;
    const int wm = (wid & 3) * 32, wn = (wid >> 2) * 32;
    const int bm = blockIdx.y * 128, bn = blockIdx.x * 64;
    const int z = blockIdx.z;
    const int g = lane >> 2, tig = lane & 3;

    const __nv_bfloat16* Bh = Bh0 + (size_t)z * DD * DD;
    const __nv_bfloat16* Bl = Bl0 + (size_t)z * DD * DD;
    __nv_bfloat16* Ch = (z == 0) ? Ch0 : (z == 1) ? Ch1 : Ch2;
    __nv_bfloat16* Cl = (z == 0) ? Cl0 : (z == 1) ? Cl1 : Cl2;
    const float scale = (SPLIT_OUT && z == 0) ? 0.125f : 1.0f;

    float acc[2][4][4];
#pragma unroll
    for (int a = 0; a < 2; a++)
#pragma unroll
        for (int b = 0; b < 4; b++)
#pragma unroll
            for (int c = 0; c < 4; c++) acc[a][b][c] = 0.0f;

    auto load_stage = [&](int s, int c) {
        const uint32_t sb = smb + s * GK_STAGE;
#pragma unroll
        for (int i = 0; i < 12; i++) {
            int u = tid + i * 256;
            if (u < 2048) {
                int arr = u >> 10;
                int w = u & 1023;
                int row = w >> 3, un = w & 7;
                const __nv_bfloat16* src = (arr ? Al : Ah) + (size_t)(bm + row) * DD + c * 64 + un * 8;
                cpa16(sb + arr * GA_SZ + gsw128(row, un), src);
            } else {
                int u2 = u - 2048;
                int arr = u2 >> 9;
                int w = u2 & 511;
                int row = w >> 3, un = w & 7;
                const __nv_bfloat16* src = (arr ? Bl : Bh) + (size_t)(bn + row) * DD + c * 64 + un * 8;
                cpa16(sb + 2 * GA_SZ + arr * GB_SZ + gsw128(row, un), src);
            }
        }
    };

    load_stage(0, 0);
    CP_COMMIT();

    for (int c = 0; c < 16; c++) {
        cp_wait<0>();
        __syncthreads();
        if (c + 1 < 16) load_stage((c + 1) & 1, c + 1);
        CP_COMMIT();

        const uint32_t sA_h = smb + (c & 1) * GK_STAGE;
        const uint32_t sA_l = sA_h + GA_SZ;
        const uint32_t sB_h = sA_h + 2 * GA_SZ;
        const uint32_t sB_l = sB_h + GB_SZ;
#pragma unroll
        for (int j = 0; j < 4; j++) {
            uint32_t ah4[2][4], al4[2][4];
#pragma unroll
            for (int mi = 0; mi < 2; mi++) {
                int row = wm + 16 * mi + (lane & 15);
                int un = 2 * j + (lane >> 4);
                uint32_t off = gsw128(row, un);
                ldsm_x4(ah4[mi], sA_h + off);
                ldsm_x4(al4[mi], sA_l + off);
            }
            uint32_t bh[4][2], bl[4][2];
#pragma unroll
            for (int p = 0; p < 2; p++) {
                int row = wn + 16 * p + ((lane >> 4) << 3) + (lane & 7);
                int un = 2 * j + ((lane >> 3) & 1);
                uint32_t off = gsw128(row, un);
                uint32_t t[4];
                ldsm_x4(t, sB_h + off);
                bh[2 * p][0] = t[0]; bh[2 * p][1] = t[1];
                bh[2 * p + 1][0] = t[2]; bh[2 * p + 1][1] = t[3];
                ldsm_x4(t, sB_l + off);
                bl[2 * p][0] = t[0]; bl[2 * p][1] = t[1];
                bl[2 * p + 1][0] = t[2]; bl[2 * p + 1][1] = t[3];
            }
#pragma unroll
            for (int t = 0; t < 3; t++)
#pragma unroll
                for (int mi = 0; mi < 2; mi++)
#pragma unroll
                    for (int ni = 0; ni < 4; ni++) {
                        const uint32_t (&af)[4] = (t == 2) ? al4[mi] : ah4[mi];
                        const uint32_t b0 = (t == 1) ? bl[ni][0] : bh[ni][0];
                        const uint32_t b1 = (t == 1) ? bl[ni][1] : bh[ni][1];
                        mma16816(acc[mi][ni], af, b0, b1);
                    }
        }
    }

    // Epilogue
#pragma unroll
    for (int mi = 0; mi < 2; mi++) {
#pragma unroll
        for (int ni = 0; ni < 4; ni++) {
            int row0 = bm + wm + 16 * mi + g;
            int col = bn + wn + 8 * ni + 2 * tig;
            float v0 = acc[mi][ni][0] * scale, v1 = acc[mi][ni][1] * scale;
            float v2 = acc[mi][ni][2] * scale, v3 = acc[mi][ni][3] * scale;
            if (SPLIT_OUT) {
                uint32_t h, l;
                split_pack(v0, v1, h, l);
                *(uint32_t*)(Ch + (size_t)row0 * DD + col) = h;
                *(uint32_t*)(Cl + (size_t)row0 * DD + col) = l;
                split_pack(v2, v3, h, l);
                *(uint32_t*)(Ch + (size_t)(row0 + 8) * DD + col) = h;
                *(uint32_t*)(Cl + (size_t)(row0 + 8) * DD + col) = l;
            } else {
                *(float2*)(Cf + (size_t)row0 * DD + col) = make_float2(v0, v1);
                *(float2*)(Cf + (size_t)(row0 + 8) * DD + col) = make_float2(v2, v3);
            }
        }
    }
}

// ---------------------------------------------------------------------------
// Flash attention — R7 structure (3-stage ring, 1 barrier/tile, 2 CTAs/SM)
// with R13 change: MMA chains reordered term-major with all 4 p-fragments
// preloaded, raising accumulator reuse distance from 2 to 8.
// ---------------------------------------------------------------------------
#define AT_ASZ (64 * 72 * 2)     // 9216 per array
#define AT_STAGE (4 * AT_ASZ)    // 36864
#define ATTN_SMEM (3 * AT_STAGE) // 110592

__global__ __launch_bounds__(128, 2) void attn_mma(
    const __nv_bfloat16* __restrict__ qh, const __nv_bfloat16* __restrict__ ql,
    const __nv_bfloat16* __restrict__ kh, const __nv_bfloat16* __restrict__ kl,
    const __nv_bfloat16* __restrict__ vh, const __nv_bfloat16* __restrict__ vl,
    __nv_bfloat16* __restrict__ oh, __nv_bfloat16* __restrict__ ol) {
    extern __shared__ char smc[];
    const uint32_t smb = smem_u32(smc);
    const int tid = threadIdx.x, lane = tid & 31, wid = tid >> 5;
    const int qt = (int)(gridDim.x - 1 - blockIdx.x);   // heavy tiles first
    const int h = blockIdx.y, b = blockIdx.z;
    const int qbase = qt * 64;
    const int g = lane >> 2, tig = lane & 3;
    const int wrow = 16 * wid;

    // Stage Q through slot 0 (arrays 0,1), read fragments, then reuse for KV.
    {
        const int qa = tid >> 6;
        const __nv_bfloat16* gq = qa ? ql : qh;
        uint32_t sbase = smb + qa * AT_ASZ;
        int t64 = tid & 63;
#pragma unroll
        for (int i = 0; i < 8; i++) {
            int id = i * 64 + t64;
            int row = id >> 3, ch = (id & 7) * 8;
            cpa16(sbase + (uint32_t)(row * 72 + ch) * 2,
                  gq + (size_t)(b * LL + qbase + row) * DD + h * HD + ch);
        }
    }
    CP_COMMIT();
    cp_wait<0>();
    __syncthreads();

    uint32_t qfh[4][4], qfl[4][4];
#pragma unroll
    for (int j = 0; j < 4; j++) {
        uint32_t off = (uint32_t)(((wrow + (lane & 15)) * 72 +
                                   16 * j + ((lane >> 4) << 3)) * 2);
        ldsm_x4(qfh[j], smb + off);
        ldsm_x4(qfl[j], smb + AT_ASZ + off);
    }
    __syncthreads();   // all warps done reading Q before KV overwrites slot 0

    const int arr = wid;   // 0:Kh 1:Kl 2:Vh 3:Vl
    const __nv_bfloat16* gkv = (arr == 0) ? kh : (arr == 1) ? kl : (arr == 2) ? vh : vl;
    auto load_kv = [&](int st, int kb) {
        uint32_t sbase = smb + st * AT_STAGE + arr * AT_ASZ;
#pragma unroll
        for (int i = 0; i < 16; i++) {
            int id = i * 32 + lane;
            int row = id >> 3, ch = (id & 7) * 8;
            cpa16(sbase + (uint32_t)(row * 72 + ch) * 2,
                  gkv + (size_t)(b * LL + kb + row) * DD + h * HD + ch);
        }
    };

    const int nkt = qt + 1;
    load_kv(0, 0);
    CP_COMMIT();
    load_kv(1, 64);
    CP_COMMIT();

    float l0 = 0.0f, l1 = 0.0f;
    float o[8][4];
#pragma unroll
    for (int f = 0; f < 8; f++)
#pragma unroll
        for (int r = 0; r < 4; r++) o[f][r] = 0.0f;

    for (int kt = 0; kt < nkt; kt++) {
        cp_wait<1>();
        __syncthreads();   // publish tile kt; proves reads of slot (kt+2)%3 done

        const int kb = kt * 64;
        const int st = kt % 3;
        const uint32_t sKh = smb + st * AT_STAGE;
        const uint32_t sKl = sKh + AT_ASZ;
        const uint32_t sVh = sKh + 2 * AT_ASZ;
        const uint32_t sVl = sKh + 3 * AT_ASZ;

        float sf[8][4];
#pragma unroll
        for (int f = 0; f < 8; f++)
#pragma unroll
            for (int r = 0; r < 4; r++) sf[f][r] = 0.0f;

        // S = Qh*Kh + Qh*Kl + Ql*Kh — term-major, acc reuse distance 8.
#pragma unroll
        for (int jj = 0; jj < 4; jj++) {
            uint32_t th[4][4], tl[4][4];
#pragma unroll
            for (int p = 0; p < 4; p++) {
                uint32_t off = (uint32_t)(((16 * p + ((lane >> 4) << 3) + (lane & 7)) * 72 +
                                           16 * jj + ((lane >> 3) & 1) * 8) * 2);
                ldsm_x4(th[p], sKh + off);
                ldsm_x4(tl[p], sKl + off);
            }
#pragma unroll
            for (int p = 0; p < 4; p++) {
                mma16816(sf[2 * p],     qfh[jj], th[p][0], th[p][1]);
                mma16816(sf[2 * p + 1], qfh[jj], th[p][2], th[p][3]);
            }
#pragma unroll
            for (int p = 0; p < 4; p++) {
                mma16816(sf[2 * p],     qfh[jj], tl[p][0], tl[p][1]);
                mma16816(sf[2 * p + 1], qfh[jj], tl[p][2], tl[p][3]);
            }
#pragma unroll
            for (int p = 0; p < 4; p++) {
                mma16816(sf[2 * p],     qfl[jj], th[p][0], th[p][1]);
                mma16816(sf[2 * p + 1], qfl[jj], th[p][2], th[p][3]);
            }
        }

        if (kt + 2 < nkt) load_kv((kt + 2) % 3, (kt + 2) * 64);
        CP_COMMIT();

        const int row0 = qbase + wrow + g, row1 = row0 + 8;
        if (kb + 63 > qbase + wrow) {  // diagonal tile: causal mask
#pragma unroll
            for (int f = 0; f < 8; f++) {
                int col = kb + 8 * f + 2 * tig;
                if (col > row0) sf[f][0] = -1e30f;
                if (col + 1 > row0) sf[f][1] = -1e30f;
                if (col > row1) sf[f][2] = -1e30f;
                if (col + 1 > row1) sf[f][3] = -1e30f;
            }
        }

        // Static softmax
#pragma unroll
        for (int f = 0; f < 8; f++) {
            sf[f][0] = __expf(sf[f][0]);
            sf[f][1] = __expf(sf[f][1]);
            sf[f][2] = __expf(sf[f][2]);
            sf[f][3] = __expf(sf[f][3]);
            l0 += sf[f][0] + sf[f][1];
            l1 += sf[f][2] + sf[f][3];
        }

        // O += Ph*Vh + Ph*Vl + Pl*Vh — term-major, acc reuse distance 8.
#pragma unroll
        for (int j = 0; j < 4; j++) {
            uint32_t pA_h[4], pA_l[4];
            split_pack(sf[2 * j][0], sf[2 * j][1], pA_h[0], pA_l[0]);
            split_pack(sf[2 * j][2], sf[2 * j][3], pA_h[1], pA_l[1]);
            split_pack(sf[2 * j + 1][0], sf[2 * j + 1][1], pA_h[2], pA_l[2]);
            split_pack(sf[2 * j + 1][2], sf[2 * j + 1][3], pA_h[3], pA_l[3]);
            uint32_t vh_f[4][4], vl_f[4][4];
#pragma unroll
            for (int p = 0; p < 4; p++) {
                uint32_t off = (uint32_t)(((16 * j + ((lane >> 3) & 1) * 8 + (lane & 7)) * 72 +
                                           16 * p + (lane >> 4) * 8) * 2);
                ldsm_x4_t(vh_f[p], sVh + off);
                ldsm_x4_t(vl_f[p], sVl + off);
            }
#pragma unroll
            for (int p = 0; p < 4; p++) {
                mma16816(o[2 * p],     pA_h, vh_f[p][0], vh_f[p][1]);
                mma16816(o[2 * p + 1], pA_h, vh_f[p][2], vh_f[p][3]);
            }
#pragma unroll
            for (int p = 0; p < 4; p++) {
                mma16816(o[2 * p],     pA_h, vl_f[p][0], vl_f[p][1]);
                mma16816(o[2 * p + 1], pA_h, vl_f[p][2], vl_f[p][3]);
            }
#pragma unroll
            for (int p = 0; p < 4; p++) {
                mma16816(o[2 * p],     pA_l, vh_f[p][0], vh_f[p][1]);
                mma16816(o[2 * p + 1], pA_l, vh_f[p][2], vh_f[p][3]);
            }
        }
        // NO tail barrier: next iteration's top barrier provides the ordering.
    }

    l0 += __shfl_xor_sync(0xffffffffu, l0, 1);
    l0 += __shfl_xor_sync(0xffffffffu, l0, 2);
    l1 += __shfl_xor_sync(0xffffffffu, l1, 1);
    l1 += __shfl_xor_sync(0xffffffffu, l1, 2);
    const float i0 = 1.0f / l0, i1 = 1.0f / l1;
    const size_t grow0 = (size_t)(b * LL + qbase + wrow + g);
    const size_t grow1 = grow0 + 8;
#pragma unroll
    for (int f = 0; f < 8; f++) {
        int col = h * HD + 8 * f + 2 * tig;
        uint32_t hi, lo;
        split_pack(o[f][0] * i0, o[f][1] * i0, hi, lo);
        *(uint32_t*)(oh + grow0 * DD + col) = hi;
        *(uint32_t*)(ol + grow0 * DD + col) = lo;
        split_pack(o[f][2] * i1, o[f][3] * i1, hi, lo);
        *(uint32_t*)(oh + grow1 * DD + col) = hi;
        *(uint32_t*)(ol + grow1 * DD + col) = lo;
    }
}

// ---------------------------------------------------------------------------
// Conversions
// ---------------------------------------------------------------------------
__global__ __launch_bounds__(256) void conv_split(const float* __restrict__ x,
                                                  __nv_bfloat16* __restrict__ xh,
                                                  __nv_bfloat16* __restrict__ xl) {
    int i = (blockIdx.x * 256 + threadIdx.x) * 4;
    float4 v = *(const float4*)(x + i);
    float f[4] = {v.x, v.y, v.z, v.w};
    __nv_bfloat16 hh[4], ll[4];
#pragma unroll
    for (int j = 0; j < 4; j++) {
        hh[j] = __float2bfloat16(f[j]);
        ll[j] = __float2bfloat16(f[j] - __bfloat162float(hh[j]));
    }
    *(uint2*)(xh + i) = *(uint2*)hh;
    *(uint2*)(xl + i) = *(uint2*)ll;
}

__global__ __launch_bounds__(256) void conv_w4(const float* __restrict__ W0,
                                               const float* __restrict__ W1,
                                               const float* __restrict__ W2,
                                               const float* __restrict__ W3,
                                               __nv_bfloat16* __restrict__ Th,
                                               __nv_bfloat16* __restrict__ Tl) {
    __shared__ float t[32][33];
    const int tx = threadIdx.x, ty = threadIdx.y;  // 32 x 8
    const int n0 = blockIdx.x * 32, k0 = blockIdx.y * 32;
    const int z = blockIdx.z;
    const float* W = (z == 0) ? W0 : (z == 1) ? W1 : (z == 2) ? W2 : W3;
    __nv_bfloat16* th = Th + (size_t)z * DD * DD;
    __nv_bfloat16* tl = Tl + (size_t)z * DD * DD;
#pragma unroll
    for (int j = 0; j < 32; j += 8)
        t[ty + j][tx] = W[(size_t)(k0 + ty + j) * DD + n0 + tx];
    __syncthreads();
#pragma unroll
    for (int j = 0; j < 32; j += 8) {
        float v = t[tx][ty + j];
        __nv_bfloat16 hh = __float2bfloat16(v);
        __nv_bfloat16 ll = __float2bfloat16(v - __bfloat162float(hh));
        th[(size_t)(n0 + ty + j) * DD + k0 + tx] = hh;
        tl[(size_t)(n0 + ty + j) * DD + k0 + tx] = ll;
    }
}

// ---------------------------------------------------------------------------
// Launch
// ---------------------------------------------------------------------------
extern "C" void kernel_launch(void* const* d_in, const int* in_sizes, int n_in,
                              void* d_out, int out_size) {
    const float* x  = (const float*)d_in[0];
    const float* Wk = (const float*)d_in[1];
    const float* Wq = (const float*)d_in[2];
    const float* Wv = (const float*)d_in[3];
    const float* Wo = (const float*)d_in[4];
    float* out = (float*)d_out;

    void *p;
#define GETP(sym, var) cudaGetSymbolAddress(&p, sym); __nv_bfloat16* var = (__nv_bfloat16*)p;
    GETP(g_xh, xh) GETP(g_xl, xl)
    GETP(g_qh, qh) GETP(g_ql, ql)
    GETP(g_kh, kh) GETP(g_kl, kl)
    GETP(g_vh, vh) GETP(g_vl, vl)
    GETP(g_ah, ah) GETP(g_al, al)
    GETP(g_wh, wh) GETP(g_wl, wl)
#undef GETP

    static bool attrs_set = false;
    if (!attrs_set) {
        cudaFuncSetAttribute(gemm_mma<true>, cudaFuncAttributeMaxDynamicSharedMemorySize, GEMM_SMEM);
        cudaFuncSetAttribute(gemm_mma<false>, cudaFuncAttributeMaxDynamicSharedMemorySize, GEMM_SMEM);
        cudaFuncSetAttribute(attn_mma, cudaFuncAttributeMaxDynamicSharedMemorySize, ATTN_SMEM);
        attrs_set = true;
    }

    // 1. conversions (weight order: 0=Wq, 1=Wk, 2=Wv, 3=Wo)
    conv_split<<<MM * DD / (256 * 4), 256>>>(x, xh, xl);
    dim3 wgrid(DD / 32, DD / 32, 4);
    dim3 wblk(32, 8);
    conv_w4<<<wgrid, wblk>>>(Wq, Wk, Wv, Wo, wh, wl);

    // 2. fused QKV projections (z: 0=Q pre-scaled 0.125, 1=K, 2=V)
    dim3 ggrid(DD / 64, MM / 128, 3);   // (16, 32, 3)
    gemm_mma<true><<<ggrid, 256, GEMM_SMEM>>>(xh, xl, wh, wl,
                                              qh, ql, kh, kl, vh, vl, nullptr);

    // 3. attention (64-row q tiles, static softmax, 3-stage ring, dist-8 MMAs)
    dim3 agrid(LL / 64, HH, BB);  // (32, 16, 2)
    attn_mma<<<agrid, 128, ATTN_SMEM>>>(qh, ql, kh, kl, vh, vl, ah, al);

    // 4. output projection (fp32 out)
    dim3 ogrid(DD / 64, MM / 128, 1);
    gemm_mma<false><<<ogrid, 256, GEMM_SMEM>>>(ah, al,
                                               wh + 3 * (size_t)DD * DD, wl + 3 * (size_t)DD * DD,
                                               nullptr, nullptr, nullptr, nullptr, nullptr, nullptr,
                                               out);
}

// round 16
// speedup vs baseline: 1.4080x; 1.2927x over previous
#include <cuda_runtime.h>
#include <cuda_bf16.h>
#include <cuda_fp16.h>
#include <cstdint>

// Problem constants
#define BB 2
#define LL 2048
#define DD 1024
#define HH 16
#define HD 64
#define MM (BB * LL)   // 4096 rows

// ---------------------------------------------------------------------------
// Scratch (device globals; no allocations allowed).
// x and attention-output stay split-bf16 (3-term GEMMs).
// q/k/v are fp16 single-precision (attention path).
// ---------------------------------------------------------------------------
__device__ __align__(1024) __nv_bfloat16 g_xh[MM * DD], g_xl[MM * DD];
__device__ __align__(1024) __half        g_q16[MM * DD];
__device__ __align__(1024) __half        g_k16[MM * DD];
__device__ __align__(1024) __half        g_v16[MM * DD];
__device__ __align__(1024) __nv_bfloat16 g_ah[MM * DD], g_al[MM * DD];
__device__ __align__(1024) __nv_bfloat16 g_wh[4][DD * DD], g_wl[4][DD * DD];

// ---------------------------------------------------------------------------
// Helpers (base sm_103-safe: mma.sync / ldmatrix / cp.async only)
// ---------------------------------------------------------------------------
__device__ __forceinline__ uint32_t smem_u32(const void* p) {
    uint32_t a;
    asm("{ .reg .u64 t; cvta.to.shared.u64 t, %1; cvt.u32.u64 %0, t; }" : "=r"(a) : "l"(p));
    return a;
}
__device__ __forceinline__ void cpa16(uint32_t dst, const void* src) {
    asm volatile("cp.async.cg.shared.global [%0], [%1], 16;" :: "r"(dst), "l"(src));
}
#define CP_COMMIT() asm volatile("cp.async.commit_group;" ::: "memory")
template <int N>
__device__ __forceinline__ void cp_wait() {
    asm volatile("cp.async.wait_group %0;" :: "n"(N) : "memory");
}
__device__ __forceinline__ void ldsm_x4(uint32_t (&r)[4], uint32_t addr) {
    asm volatile("ldmatrix.sync.aligned.m8n8.x4.shared.b16 {%0,%1,%2,%3}, [%4];"
                 : "=r"(r[0]), "=r"(r[1]), "=r"(r[2]), "=r"(r[3]) : "r"(addr));
}
__device__ __forceinline__ void ldsm_x4_t(uint32_t (&r)[4], uint32_t addr) {
    asm volatile("ldmatrix.sync.aligned.m8n8.x4.trans.shared.b16 {%0,%1,%2,%3}, [%4];"
                 : "=r"(r[0]), "=r"(r[1]), "=r"(r[2]), "=r"(r[3]) : "r"(addr));
}
// bf16 MMA (GEMMs)
__device__ __forceinline__ void mma16816(float (&d)[4], const uint32_t (&a)[4],
                                         uint32_t b0, uint32_t b1) {
    asm volatile(
        "mma.sync.aligned.m16n8k16.row.col.f32.bf16.bf16.f32 "
        "{%0,%1,%2,%3}, {%4,%5,%6,%7}, {%8,%9}, {%0,%1,%2,%3};"
        : "+f"(d[0]), "+f"(d[1]), "+f"(d[2]), "+f"(d[3])
        : "r"(a[0]), "r"(a[1]), "r"(a[2]), "r"(a[3]), "r"(b0), "r"(b1));
}
// fp16 MMA (attention)
__device__ __forceinline__ void mma16816h(float (&d)[4], const uint32_t (&a)[4],
                                          uint32_t b0, uint32_t b1) {
    asm volatile(
        "mma.sync.aligned.m16n8k16.row.col.f32.f16.f16.f32 "
        "{%0,%1,%2,%3}, {%4,%5,%6,%7}, {%8,%9}, {%0,%1,%2,%3};"
        : "+f"(d[0]), "+f"(d[1]), "+f"(d[2]), "+f"(d[3])
        : "r"(a[0]), "r"(a[1]), "r"(a[2]), "r"(a[3]), "r"(b0), "r"(b1));
}
__device__ __forceinline__ uint32_t pack2h(float lo, float hi) {
    __half2 t = __floats2half2_rn(lo, hi);
    return *(uint32_t*)&t;
}
__device__ __forceinline__ uint32_t pack2(float lo, float hi) {
    __nv_bfloat162 t = __floats2bfloat162_rn(lo, hi);
    return *(uint32_t*)&t;
}
__device__ __forceinline__ void split_pack(float v0, float v1, uint32_t& h, uint32_t& l) {
    __nv_bfloat16 h0 = __float2bfloat16(v0), h1 = __float2bfloat16(v1);
    float l0 = v0 - __bfloat162float(h0), l1 = v1 - __bfloat162float(h1);
    __nv_bfloat162 hp; hp.x = h0; hp.y = h1;
    h = *(uint32_t*)&hp;
    l = pack2(l0, l1);
}

// ---------------------------------------------------------------------------
// Split-bf16 mma.sync GEMM — R10 winner core. Epilogue variants:
//   HALF_OUT: write fp16 single (for attention Q/K/V)
//   else:     write fp32 (output projection)
// CTA tile 128x64, BK=64, two-stage double buffer, one barrier per chunk.
// ---------------------------------------------------------------------------
#define GA_SZ (128 * 64 * 2)        // 16384 B per A array
#define GB_SZ (64 * 64 * 2)         // 8192 B per B array
#define GK_STAGE (2 * GA_SZ + 2 * GB_SZ)  // 49152 B
#define GEMM_SMEM (2 * GK_STAGE)    // 98304 B

__device__ __forceinline__ uint32_t gsw128(int row, int unit) {  // 128B-row SW128
    return (uint32_t)(row * 128 + ((unit ^ (row & 7)) << 4));
}

template <bool HALF_OUT>
__global__ __launch_bounds__(256, 2) void gemm_mma(
    const __nv_bfloat16* __restrict__ Ah, const __nv_bfloat16* __restrict__ Al,
    const __nv_bfloat16* __restrict__ Bh0, const __nv_bfloat16* __restrict__ Bl0,
    __half* __restrict__ H0, __half* __restrict__ H1, __half* __restrict__ H2,
    float* __restrict__ Cf) {
    extern __shared__ char smc[];
    const uint32_t smb = smem_u32(smc);
    const int tid = threadIdx.x, lane = tid & 31, wid = tid >> 5;
    const int wm = (wid & 3) * 32, wn = (wid >> 2) * 32;
    const int bm = blockIdx.y * 128, bn = blockIdx.x * 64;
    const int z = blockIdx.z;
    const int g = lane >> 2, tig = lane & 3;

    const __nv_bfloat16* Bh = Bh0 + (size_t)z * DD * DD;
    const __nv_bfloat16* Bl = Bl0 + (size_t)z * DD * DD;
    __half* Ho = (z == 0) ? H0 : (z == 1) ? H1 : H2;
    const float scale = (HALF_OUT && z == 0) ? 0.125f : 1.0f;

    float acc[2][4][4];
#pragma unroll
    for (int a = 0; a < 2; a++)
#pragma unroll
        for (int b = 0; b < 4; b++)
#pragma unroll
            for (int c = 0; c < 4; c++) acc[a][b][c] = 0.0f;

    auto load_stage = [&](int s, int c) {
        const uint32_t sb = smb + s * GK_STAGE;
#pragma unroll
        for (int i = 0; i < 12; i++) {
            int u = tid + i * 256;
            if (u < 2048) {
                int arr = u >> 10;
                int w = u & 1023;
                int row = w >> 3, un = w & 7;
                const __nv_bfloat16* src = (arr ? Al : Ah) + (size_t)(bm + row) * DD + c * 64 + un * 8;
                cpa16(sb + arr * GA_SZ + gsw128(row, un), src);
            } else {
                int u2 = u - 2048;
                int arr = u2 >> 9;
                int w = u2 & 511;
                int row = w >> 3, un = w & 7;
                const __nv_bfloat16* src = (arr ? Bl : Bh) + (size_t)(bn + row) * DD + c * 64 + un * 8;
                cpa16(sb + 2 * GA_SZ + arr * GB_SZ + gsw128(row, un), src);
            }
        }
    };

    load_stage(0, 0);
    CP_COMMIT();

    for (int c = 0; c < 16; c++) {
        cp_wait<0>();
        __syncthreads();
        if (c + 1 < 16) load_stage((c + 1) & 1, c + 1);
        CP_COMMIT();

        const uint32_t sA_h = smb + (c & 1) * GK_STAGE;
        const uint32_t sA_l = sA_h + GA_SZ;
        const uint32_t sB_h = sA_h + 2 * GA_SZ;
        const uint32_t sB_l = sB_h + GB_SZ;
#pragma unroll
        for (int j = 0; j < 4; j++) {
            uint32_t ah4[2][4], al4[2][4];
#pragma unroll
            for (int mi = 0; mi < 2; mi++) {
                int row = wm + 16 * mi + (lane & 15);
                int un = 2 * j + (lane >> 4);
                uint32_t off = gsw128(row, un);
                ldsm_x4(ah4[mi], sA_h + off);
                ldsm_x4(al4[mi], sA_l + off);
            }
            uint32_t bh[4][2], bl[4][2];
#pragma unroll
            for (int p = 0; p < 2; p++) {
                int row = wn + 16 * p + ((lane >> 4) << 3) + (lane & 7);
                int un = 2 * j + ((lane >> 3) & 1);
                uint32_t off = gsw128(row, un);
                uint32_t t[4];
                ldsm_x4(t, sB_h + off);
                bh[2 * p][0] = t[0]; bh[2 * p][1] = t[1];
                bh[2 * p + 1][0] = t[2]; bh[2 * p + 1][1] = t[3];
                ldsm_x4(t, sB_l + off);
                bl[2 * p][0] = t[0]; bl[2 * p][1] = t[1];
                bl[2 * p + 1][0] = t[2]; bl[2 * p + 1][1] = t[3];
            }
#pragma unroll
            for (int t = 0; t < 3; t++)
#pragma unroll
                for (int mi = 0; mi < 2; mi++)
#pragma unroll
                    for (int ni = 0; ni < 4; ni++) {
                        const uint32_t (&af)[4] = (t == 2) ? al4[mi] : ah4[mi];
                        const uint32_t b0 = (t == 1) ? bl[ni][0] : bh[ni][0];
                        const uint32_t b1 = (t == 1) ? bl[ni][1] : bh[ni][1];
                        mma16816(acc[mi][ni], af, b0, b1);
                    }
        }
    }

    // Epilogue
#pragma unroll
    for (int mi = 0; mi < 2; mi++) {
#pragma unroll
        for (int ni = 0; ni < 4; ni++) {
            int row0 = bm + wm + 16 * mi + g;
            int col = bn + wn + 8 * ni + 2 * tig;
            float v0 = acc[mi][ni][0] * scale, v1 = acc[mi][ni][1] * scale;
            float v2 = acc[mi][ni][2] * scale, v3 = acc[mi][ni][3] * scale;
            if (HALF_OUT) {
                *(uint32_t*)(Ho + (size_t)row0 * DD + col) = pack2h(v0, v1);
                *(uint32_t*)(Ho + (size_t)(row0 + 8) * DD + col) = pack2h(v2, v3);
            } else {
                *(float2*)(Cf + (size_t)row0 * DD + col) = make_float2(v0, v1);
                *(float2*)(Cf + (size_t)(row0 + 8) * DD + col) = make_float2(v2, v3);
            }
        }
    }
}

// ---------------------------------------------------------------------------
// Flash attention — fp16 single-term path (R15).
// R7 pipeline: 3-stage KV ring, 1 barrier/tile, prefetch after S block.
// Stage = K(9216) + V(9216) = 18432 B; 3 stages = 55296 B -> 3 CTAs/SM.
// MMAs/tile: 64 (32 S + 32 PV). Output remains split-bf16 for 3-term O-proj.
// ---------------------------------------------------------------------------
#define AT_ASZ (64 * 72 * 2)     // 9216 per array (72-halfword padded rows)
#define AT_STAGE (2 * AT_ASZ)    // 18432 (K, V)
#define ATTN_SMEM (3 * AT_STAGE) // 55296

__global__ __launch_bounds__(128, 3) void attn_mma(
    const __half* __restrict__ q,
    const __half* __restrict__ k,
    const __half* __restrict__ v,
    __nv_bfloat16* __restrict__ oh, __nv_bfloat16* __restrict__ ol) {
    extern __shared__ char smc[];
    const uint32_t smb = smem_u32(smc);
    const int tid = threadIdx.x, lane = tid & 31, wid = tid >> 5;
    const int qt = (int)(gridDim.x - 1 - blockIdx.x);   // heavy tiles first
    const int h = blockIdx.y, b = blockIdx.z;
    const int qbase = qt * 64;
    const int g = lane >> 2, tig = lane & 3;
    const int wrow = 16 * wid;

    // Stage Q through slot 0's K array, read fragments, then reuse for KV.
    {
#pragma unroll
        for (int i = 0; i < 4; i++) {
            int id = i * 128 + tid;
            int row = id >> 3, ch = (id & 7) * 8;
            cpa16(smb + (uint32_t)(row * 72 + ch) * 2,
                  q + (size_t)(b * LL + qbase + row) * DD + h * HD + ch);
        }
    }
    CP_COMMIT();
    cp_wait<0>();
    __syncthreads();

    uint32_t qf[4][4];
#pragma unroll
    for (int j = 0; j < 4; j++) {
        uint32_t off = (uint32_t)(((wrow + (lane & 15)) * 72 +
                                   16 * j + ((lane >> 4) << 3)) * 2);
        ldsm_x4(qf[j], smb + off);
    }
    __syncthreads();   // all warps done reading Q before KV overwrites slot 0

    // KV loader: warps 0,1 -> K rows [0,32)/[32,64); warps 2,3 -> V likewise.
    const __half* gkv = (wid >> 1) ? v : k;
    const int rbase = (wid & 1) * 32;
    auto load_kv = [&](int st, int kb) {
        uint32_t sbase = smb + st * AT_STAGE + (wid >> 1) * AT_ASZ;
#pragma unroll
        for (int i = 0; i < 8; i++) {
            int id = i * 32 + lane;
            int row = rbase + (id >> 3), ch = (id & 7) * 8;
            cpa16(sbase + (uint32_t)(row * 72 + ch) * 2,
                  gkv + (size_t)(b * LL + kb + row) * DD + h * HD + ch);
        }
    };

    const int nkt = qt + 1;
    load_kv(0, 0);
    CP_COMMIT();
    load_kv(1, 64);
    CP_COMMIT();

    float l0 = 0.0f, l1 = 0.0f;
    float o[8][4];
#pragma unroll
    for (int f = 0; f < 8; f++)
#pragma unroll
        for (int r = 0; r < 4; r++) o[f][r] = 0.0f;

    for (int kt = 0; kt < nkt; kt++) {
        cp_wait<1>();
        __syncthreads();   // publish tile kt; proves reads of slot (kt+2)%3 done

        const int kb = kt * 64;
        const int st = kt % 3;
        const uint32_t sK = smb + st * AT_STAGE;
        const uint32_t sV = sK + AT_ASZ;

        float sf[8][4];
#pragma unroll
        for (int f = 0; f < 8; f++)
#pragma unroll
            for (int r = 0; r < 4; r++) sf[f][r] = 0.0f;

        // S = Q * K^T (fp16 single term) — 8 accs, reuse distance 8.
#pragma unroll
        for (int jj = 0; jj < 4; jj++) {
            uint32_t th[4][4];
#pragma unroll
            for (int p = 0; p < 4; p++) {
                uint32_t off = (uint32_t)(((16 * p + ((lane >> 4) << 3) + (lane & 7)) * 72 +
                                           16 * jj + ((lane >> 3) & 1) * 8) * 2);
                ldsm_x4(th[p], sK + off);
            }
#pragma unroll
            for (int p = 0; p < 4; p++) {
                mma16816h(sf[2 * p],     qf[jj], th[p][0], th[p][1]);
                mma16816h(sf[2 * p + 1], qf[jj], th[p][2], th[p][3]);
            }
        }

        if (kt + 2 < nkt) load_kv((kt + 2) % 3, (kt + 2) * 64);
        CP_COMMIT();

        const int row0 = qbase + wrow + g, row1 = row0 + 8;
        if (kb + 63 > qbase + wrow) {  // diagonal tile: causal mask
#pragma unroll
            for (int f = 0; f < 8; f++) {
                int col = kb + 8 * f + 2 * tig;
                if (col > row0) sf[f][0] = -1e30f;
                if (col + 1 > row0) sf[f][1] = -1e30f;
                if (col > row1) sf[f][2] = -1e30f;
                if (col + 1 > row1) sf[f][3] = -1e30f;
            }
        }

        // Static softmax
#pragma unroll
        for (int f = 0; f < 8; f++) {
            sf[f][0] = __expf(sf[f][0]);
            sf[f][1] = __expf(sf[f][1]);
            sf[f][2] = __expf(sf[f][2]);
            sf[f][3] = __expf(sf[f][3]);
            l0 += sf[f][0] + sf[f][1];
            l1 += sf[f][2] + sf[f][3];
        }

        // O += P * V (fp16 single term)
#pragma unroll
        for (int j = 0; j < 4; j++) {
            uint32_t pA[4];
            pA[0] = pack2h(sf[2 * j][0], sf[2 * j][1]);
            pA[1] = pack2h(sf[2 * j][2], sf[2 * j][3]);
            pA[2] = pack2h(sf[2 * j + 1][0], sf[2 * j + 1][1]);
            pA[3] = pack2h(sf[2 * j + 1][2], sf[2 * j + 1][3]);
            uint32_t vf[4][4];
#pragma unroll
            for (int p = 0; p < 4; p++) {
                uint32_t off = (uint32_t)(((16 * j + ((lane >> 3) & 1) * 8 + (lane & 7)) * 72 +
                                           16 * p + (lane >> 4) * 8) * 2);
                ldsm_x4_t(vf[p], sV + off);
            }
#pragma unroll
            for (int p = 0; p < 4; p++) {
                mma16816h(o[2 * p],     pA, vf[p][0], vf[p][1]);
                mma16816h(o[2 * p + 1], pA, vf[p][2], vf[p][3]);
            }
        }
        // NO tail barrier: next iteration's top barrier provides the ordering.
    }

    l0 += __shfl_xor_sync(0xffffffffu, l0, 1);
    l0 += __shfl_xor_sync(0xffffffffu, l0, 2);
    l1 += __shfl_xor_sync(0xffffffffu, l1, 1);
    l1 += __shfl_xor_sync(0xffffffffu, l1, 2);
    const float i0 = 1.0f / l0, i1 = 1.0f / l1;
    const size_t grow0 = (size_t)(b * LL + qbase + wrow + g);
    const size_t grow1 = grow0 + 8;
#pragma unroll
    for (int f = 0; f < 8; f++) {
        int col = h * HD + 8 * f + 2 * tig;
        uint32_t hi, lo;
        split_pack(o[f][0] * i0, o[f][1] * i0, hi, lo);
        *(uint32_t*)(oh + grow0 * DD + col) = hi;
        *(uint32_t*)(ol + grow0 * DD + col) = lo;
        split_pack(o[f][2] * i1, o[f][3] * i1, hi, lo);
        *(uint32_t*)(oh + grow1 * DD + col) = hi;
        *(uint32_t*)(ol + grow1 * DD + col) = lo;
    }
}

// ---------------------------------------------------------------------------
// Conversions
// ---------------------------------------------------------------------------
__global__ __launch_bounds__(256) void conv_split(const float* __restrict__ x,
                                                  __nv_bfloat16* __restrict__ xh,
                                                  __nv_bfloat16* __restrict__ xl) {
    int i = (blockIdx.x * 256 + threadIdx.x) * 4;
    float4 v = *(const float4*)(x + i);
    float f[4] = {v.x, v.y, v.z, v.w};
    __nv_bfloat16 hh[4], ll[4];
#pragma unroll
    for (int j = 0; j < 4; j++) {
        hh[j] = __float2bfloat16(f[j]);
        ll[j] = __float2bfloat16(f[j] - __bfloat162float(hh[j]));
    }
    *(uint2*)(xh + i) = *(uint2*)hh;
    *(uint2*)(xl + i) = *(uint2*)ll;
}

__global__ __launch_bounds__(256) void conv_w4(const float* __restrict__ W0,
                                               const float* __restrict__ W1,
                                               const float* __restrict__ W2,
                                               const float* __restrict__ W3,
                                               __nv_bfloat16* __restrict__ Th,
                                               __nv_bfloat16* __restrict__ Tl) {
    __shared__ float t[32][33];
    const int tx = threadIdx.x, ty = threadIdx.y;  // 32 x 8
    const int n0 = blockIdx.x * 32, k0 = blockIdx.y * 32;
    const int z = blockIdx.z;
    const float* W = (z == 0) ? W0 : (z == 1) ? W1 : (z == 2) ? W2 : W3;
    __nv_bfloat16* th = Th + (size_t)z * DD * DD;
    __nv_bfloat16* tl = Tl + (size_t)z * DD * DD;
#pragma unroll
    for (int j = 0; j < 32; j += 8)
        t[ty + j][tx] = W[(size_t)(k0 + ty + j) * DD + n0 + tx];
    __syncthreads();
#pragma unroll
    for (int j = 0; j < 32; j += 8) {
        float v = t[tx][ty + j];
        __nv_bfloat16 hh = __float2bfloat16(v);
        __nv_bfloat16 ll = __float2bfloat16(v - __bfloat162float(hh));
        th[(size_t)(n0 + ty + j) * DD + k0 + tx] = hh;
        tl[(size_t)(n0 + ty + j) * DD + k0 + tx] = ll;
    }
}

// ---------------------------------------------------------------------------
// Launch
// ---------------------------------------------------------------------------
extern "C" void kernel_launch(void* const* d_in, const int* in_sizes, int n_in,
                              void* d_out, int out_size) {
    const float* x  = (const float*)d_in[0];
    const float* Wk = (const float*)d_in[1];
    const float* Wq = (const float*)d_in[2];
    const float* Wv = (const float*)d_in[3];
    const float* Wo = (const float*)d_in[4];
    float* out = (float*)d_out;

    void *p;
    cudaGetSymbolAddress(&p, g_xh);  __nv_bfloat16* xh = (__nv_bfloat16*)p;
    cudaGetSymbolAddress(&p, g_xl);  __nv_bfloat16* xl = (__nv_bfloat16*)p;
    cudaGetSymbolAddress(&p, g_q16); __half* q16 = (__half*)p;
    cudaGetSymbolAddress(&p, g_k16); __half* k16 = (__half*)p;
    cudaGetSymbolAddress(&p, g_v16); __half* v16 = (__half*)p;
    cudaGetSymbolAddress(&p, g_ah);  __nv_bfloat16* ah = (__nv_bfloat16*)p;
    cudaGetSymbolAddress(&p, g_al);  __nv_bfloat16* al = (__nv_bfloat16*)p;
    cudaGetSymbolAddress(&p, g_wh);  __nv_bfloat16* wh = (__nv_bfloat16*)p;
    cudaGetSymbolAddress(&p, g_wl);  __nv_bfloat16* wl = (__nv_bfloat16*)p;

    static bool attrs_set = false;
    if (!attrs_set) {
        cudaFuncSetAttribute(gemm_mma<true>, cudaFuncAttributeMaxDynamicSharedMemorySize, GEMM_SMEM);
        cudaFuncSetAttribute(gemm_mma<false>, cudaFuncAttributeMaxDynamicSharedMemorySize, GEMM_SMEM);
        cudaFuncSetAttribute(attn_mma, cudaFuncAttributeMaxDynamicSharedMemorySize, ATTN_SMEM);
        attrs_set = true;
    }

    // 1. conversions (weight order: 0=Wq, 1=Wk, 2=Wv, 3=Wo)
    conv_split<<<MM * DD / (256 * 4), 256>>>(x, xh, xl);
    dim3 wgrid(DD / 32, DD / 32, 4);
    dim3 wblk(32, 8);
    conv_w4<<<wgrid, wblk>>>(Wq, Wk, Wv, Wo, wh, wl);

    // 2. fused QKV projections -> fp16 (z: 0=Q pre-scaled 0.125, 1=K, 2=V)
    dim3 ggrid(DD / 64, MM / 128, 3);   // (16, 32, 3)
    gemm_mma<true><<<ggrid, 256, GEMM_SMEM>>>(xh, xl, wh, wl,
                                              q16, k16, v16, nullptr);

    // 3. attention (fp16 single-term S and PV; output split-bf16)
    dim3 agrid(LL / 64, HH, BB);  // (32, 16, 2)
    attn_mma<<<agrid, 128, ATTN_SMEM>>>(q16, k16, v16, ah, al);

    // 4. output projection (3-term split-bf16, fp32 out)
    dim3 ogrid(DD / 64, MM / 128, 1);
    gemm_mma<false><<<ogrid, 256, GEMM_SMEM>>>(ah, al,
                                               wh + 3 * (size_t)DD * DD, wl + 3 * (size_t)DD * DD,
                                               nullptr, nullptr, nullptr,
                                               out);
}

// round 17
// speedup vs baseline: 1.9861x; 1.4105x over previous
#include <cuda_runtime.h>
#include <cuda_bf16.h>
#include <cuda_fp16.h>
#include <cstdint>

// Problem constants
#define BB 2
#define LL 2048
#define DD 1024
#define HH 16
#define HD 64
#define MM (BB * LL)   // 4096 rows

// ---------------------------------------------------------------------------
// Scratch (device globals; no allocations allowed).
// QKV path: all fp16 single. O-proj path: split-bf16 (3-term, precision hedge).
// ---------------------------------------------------------------------------
__device__ __align__(1024) __half        g_x16[MM * DD];
__device__ __align__(1024) __half        g_w16[3][DD * DD];   // Wq,Wk,Wv transposed fp16
__device__ __align__(1024) __half        g_q16[MM * DD];
__device__ __align__(1024) __half        g_k16[MM * DD];
__device__ __align__(1024) __half        g_v16[MM * DD];
__device__ __align__(1024) __nv_bfloat16 g_ah[MM * DD], g_al[MM * DD];
__device__ __align__(1024) __nv_bfloat16 g_woh[DD * DD], g_wol[DD * DD];

// ---------------------------------------------------------------------------
// Helpers (base sm_103-safe: mma.sync / ldmatrix / cp.async only)
// ---------------------------------------------------------------------------
__device__ __forceinline__ uint32_t smem_u32(const void* p) {
    uint32_t a;
    asm("{ .reg .u64 t; cvta.to.shared.u64 t, %1; cvt.u32.u64 %0, t; }" : "=r"(a) : "l"(p));
    return a;
}
__device__ __forceinline__ void cpa16(uint32_t dst, const void* src) {
    asm volatile("cp.async.cg.shared.global [%0], [%1], 16;" :: "r"(dst), "l"(src));
}
#define CP_COMMIT() asm volatile("cp.async.commit_group;" ::: "memory")
template <int N>
__device__ __forceinline__ void cp_wait() {
    asm volatile("cp.async.wait_group %0;" :: "n"(N) : "memory");
}
__device__ __forceinline__ void ldsm_x4(uint32_t (&r)[4], uint32_t addr) {
    asm volatile("ldmatrix.sync.aligned.m8n8.x4.shared.b16 {%0,%1,%2,%3}, [%4];"
                 : "=r"(r[0]), "=r"(r[1]), "=r"(r[2]), "=r"(r[3]) : "r"(addr));
}
__device__ __forceinline__ void ldsm_x4_t(uint32_t (&r)[4], uint32_t addr) {
    asm volatile("ldmatrix.sync.aligned.m8n8.x4.trans.shared.b16 {%0,%1,%2,%3}, [%4];"
                 : "=r"(r[0]), "=r"(r[1]), "=r"(r[2]), "=r"(r[3]) : "r"(addr));
}
// bf16 MMA (O-projection)
__device__ __forceinline__ void mma16816(float (&d)[4], const uint32_t (&a)[4],
                                         uint32_t b0, uint32_t b1) {
    asm volatile(
        "mma.sync.aligned.m16n8k16.row.col.f32.bf16.bf16.f32 "
        "{%0,%1,%2,%3}, {%4,%5,%6,%7}, {%8,%9}, {%0,%1,%2,%3};"
        : "+f"(d[0]), "+f"(d[1]), "+f"(d[2]), "+f"(d[3])
        : "r"(a[0]), "r"(a[1]), "r"(a[2]), "r"(a[3]), "r"(b0), "r"(b1));
}
// fp16 MMA (QKV GEMM + attention)
__device__ __forceinline__ void mma16816h(float (&d)[4], const uint32_t (&a)[4],
                                          uint32_t b0, uint32_t b1) {
    asm volatile(
        "mma.sync.aligned.m16n8k16.row.col.f32.f16.f16.f32 "
        "{%0,%1,%2,%3}, {%4,%5,%6,%7}, {%8,%9}, {%0,%1,%2,%3};"
        : "+f"(d[0]), "+f"(d[1]), "+f"(d[2]), "+f"(d[3])
        : "r"(a[0]), "r"(a[1]), "r"(a[2]), "r"(a[3]), "r"(b0), "r"(b1));
}
__device__ __forceinline__ uint32_t pack2h(float lo, float hi) {
    __half2 t = __floats2half2_rn(lo, hi);
    return *(uint32_t*)&t;
}
__device__ __forceinline__ uint32_t pack2(float lo, float hi) {
    __nv_bfloat162 t = __floats2bfloat162_rn(lo, hi);
    return *(uint32_t*)&t;
}
__device__ __forceinline__ void split_pack(float v0, float v1, uint32_t& h, uint32_t& l) {
    __nv_bfloat16 h0 = __float2bfloat16(v0), h1 = __float2bfloat16(v1);
    float l0 = v0 - __bfloat162float(h0), l1 = v1 - __bfloat162float(h1);
    __nv_bfloat162 hp; hp.x = h0; hp.y = h1;
    h = *(uint32_t*)&hp;
    l = pack2(l0, l1);
}

__device__ __forceinline__ uint32_t gsw128(int row, int unit) {  // 128B-row SW128
    return (uint32_t)(row * 128 + ((unit ^ (row & 7)) << 4));
}

// ---------------------------------------------------------------------------
// fp16 single-term GEMM (QKV): C16[M,N] = A16[M,K] * W16t[N,K]^T, fp16 out.
// CTA tile 128x64, BK=64, 2-stage double buffer, one barrier per chunk.
// Stage = 16KB (A) + 8KB (B) = 24KB; 2 stages = 48KB.
// ---------------------------------------------------------------------------
#define H_A_SZ (128 * 64 * 2)       // 16384
#define H_B_SZ (64 * 64 * 2)        // 8192
#define H_STAGE (H_A_SZ + H_B_SZ)   // 24576
#define GEMM16_SMEM (2 * H_STAGE)   // 49152

__global__ __launch_bounds__(256, 2) void gemm16(
    const __half* __restrict__ A, const __half* __restrict__ B0,
    __half* __restrict__ H0, __half* __restrict__ H1, __half* __restrict__ H2) {
    extern __shared__ char smc[];
    const uint32_t smb = smem_u32(smc);
    const int tid = threadIdx.x, lane = tid & 31, wid = tid >> 5;
    const int wm = (wid & 3) * 32, wn = (wid >> 2) * 32;
    const int bm = blockIdx.y * 128, bn = blockIdx.x * 64;
    const int z = blockIdx.z;
    const int g = lane >> 2, tig = lane & 3;

    const __half* B = B0 + (size_t)z * DD * DD;
    __half* Ho = (z == 0) ? H0 : (z == 1) ? H1 : H2;
    const float scale = (z == 0) ? 0.125f : 1.0f;

    float acc[2][4][4];
#pragma unroll
    for (int a = 0; a < 2; a++)
#pragma unroll
        for (int b = 0; b < 4; b++)
#pragma unroll
            for (int c = 0; c < 4; c++) acc[a][b][c] = 0.0f;

    // Stage loader: 1536 16B units (A: 1024, B: 512); 256 threads x 6.
    auto load_stage = [&](int s, int c) {
        const uint32_t sb = smb + s * H_STAGE;
#pragma unroll
        for (int i = 0; i < 6; i++) {
            int u = tid + i * 256;
            if (u < 1024) {
                int row = u >> 3, un = u & 7;
                cpa16(sb + gsw128(row, un),
                      A + (size_t)(bm + row) * DD + c * 64 + un * 8);
            } else {
                int u2 = u - 1024;
                int row = u2 >> 3, un = u2 & 7;
                cpa16(sb + H_A_SZ + gsw128(row, un),
                      B + (size_t)(bn + row) * DD + c * 64 + un * 8);
            }
        }
    };

    load_stage(0, 0);
    CP_COMMIT();

    for (int c = 0; c < 16; c++) {
        cp_wait<0>();
        __syncthreads();
        if (c + 1 < 16) load_stage((c + 1) & 1, c + 1);
        CP_COMMIT();

        const uint32_t sA = smb + (c & 1) * H_STAGE;
        const uint32_t sB = sA + H_A_SZ;
#pragma unroll
        for (int j = 0; j < 4; j++) {
            uint32_t a4[2][4];
#pragma unroll
            for (int mi = 0; mi < 2; mi++) {
                int row = wm + 16 * mi + (lane & 15);
                int un = 2 * j + (lane >> 4);
                ldsm_x4(a4[mi], sA + gsw128(row, un));
            }
            uint32_t bf[4][2];
#pragma unroll
            for (int p = 0; p < 2; p++) {
                int row = wn + 16 * p + ((lane >> 4) << 3) + (lane & 7);
                int un = 2 * j + ((lane >> 3) & 1);
                uint32_t t[4];
                ldsm_x4(t, sB + gsw128(row, un));
                bf[2 * p][0] = t[0]; bf[2 * p][1] = t[1];
                bf[2 * p + 1][0] = t[2]; bf[2 * p + 1][1] = t[3];
            }
#pragma unroll
            for (int mi = 0; mi < 2; mi++)
#pragma unroll
                for (int ni = 0; ni < 4; ni++)
                    mma16816h(acc[mi][ni], a4[mi], bf[ni][0], bf[ni][1]);
        }
    }

    // Epilogue: fp16 out
#pragma unroll
    for (int mi = 0; mi < 2; mi++) {
#pragma unroll
        for (int ni = 0; ni < 4; ni++) {
            int row0 = bm + wm + 16 * mi + g;
            int col = bn + wn + 8 * ni + 2 * tig;
            *(uint32_t*)(Ho + (size_t)row0 * DD + col) =
                pack2h(acc[mi][ni][0] * scale, acc[mi][ni][1] * scale);
            *(uint32_t*)(Ho + (size_t)(row0 + 8) * DD + col) =
                pack2h(acc[mi][ni][2] * scale, acc[mi][ni][3] * scale);
        }
    }
}

// ---------------------------------------------------------------------------
// Split-bf16 3-term GEMM (O-projection only) — R10 winner core, fp32 out.
// ---------------------------------------------------------------------------
#define GA_SZ (128 * 64 * 2)        // 16384
#define GB_SZ (64 * 64 * 2)         // 8192
#define GK_STAGE (2 * GA_SZ + 2 * GB_SZ)  // 49152
#define GEMM_SMEM (2 * GK_STAGE)    // 98304

__global__ __launch_bounds__(256, 2) void gemm_bf3(
    const __nv_bfloat16* __restrict__ Ah, const __nv_bfloat16* __restrict__ Al,
    const __nv_bfloat16* __restrict__ Bh, const __nv_bfloat16* __restrict__ Bl,
    float* __restrict__ Cf) {
    extern __shared__ char smc[];
    const uint32_t smb = smem_u32(smc);
    const int tid = threadIdx.x, lane = tid & 31, wid = tid >> 5;
    const int wm = (wid & 3) * 32, wn = (wid >> 2) * 32;
    const int bm = blockIdx.y * 128, bn = blockIdx.x * 64;
    const int g = lane >> 2, tig = lane & 3;

    float acc[2][4][4];
#pragma unroll
    for (int a = 0; a < 2; a++)
#pragma unroll
        for (int b = 0; b < 4; b++)
#pragma unroll
            for (int c = 0; c < 4; c++) acc[a][b][c] = 0.0f;

    auto load_stage = [&](int s, int c) {
        const uint32_t sb = smb + s * GK_STAGE;
#pragma unroll
        for (int i = 0; i < 12; i++) {
            int u = tid + i * 256;
            if (u < 2048) {
                int arr = u >> 10;
                int w = u & 1023;
                int row = w >> 3, un = w & 7;
                const __nv_bfloat16* src = (arr ? Al : Ah) + (size_t)(bm + row) * DD + c * 64 + un * 8;
                cpa16(sb + arr * GA_SZ + gsw128(row, un), src);
            } else {
                int u2 = u - 2048;
                int arr = u2 >> 9;
                int w = u2 & 511;
                int row = w >> 3, un = w & 7;
                const __nv_bfloat16* src = (arr ? Bl : Bh) + (size_t)(bn + row) * DD + c * 64 + un * 8;
                cpa16(sb + 2 * GA_SZ + arr * GB_SZ + gsw128(row, un), src);
            }
        }
    };

    load_stage(0, 0);
    CP_COMMIT();

    for (int c = 0; c < 16; c++) {
        cp_wait<0>();
        __syncthreads();
        if (c + 1 < 16) load_stage((c + 1) & 1, c + 1);
        CP_COMMIT();

        const uint32_t sA_h = smb + (c & 1) * GK_STAGE;
        const uint32_t sA_l = sA_h + GA_SZ;
        const uint32_t sB_h = sA_h + 2 * GA_SZ;
        const uint32_t sB_l = sB_h + GB_SZ;
#pragma unroll
        for (int j = 0; j < 4; j++) {
            uint32_t ah4[2][4], al4[2][4];
#pragma unroll
            for (int mi = 0; mi < 2; mi++) {
                int row = wm + 16 * mi + (lane & 15);
                int un = 2 * j + (lane >> 4);
                uint32_t off = gsw128(row, un);
                ldsm_x4(ah4[mi], sA_h + off);
                ldsm_x4(al4[mi], sA_l + off);
            }
            uint32_t bh[4][2], bl[4][2];
#pragma unroll
            for (int p = 0; p < 2; p++) {
                int row = wn + 16 * p + ((lane >> 4) << 3) + (lane & 7);
                int un = 2 * j + ((lane >> 3) & 1);
                uint32_t off = gsw128(row, un);
                uint32_t t[4];
                ldsm_x4(t, sB_h + off);
                bh[2 * p][0] = t[0]; bh[2 * p][1] = t[1];
                bh[2 * p + 1][0] = t[2]; bh[2 * p + 1][1] = t[3];
                ldsm_x4(t, sB_l + off);
                bl[2 * p][0] = t[0]; bl[2 * p][1] = t[1];
                bl[2 * p + 1][0] = t[2]; bl[2 * p + 1][1] = t[3];
            }
#pragma unroll
            for (int t = 0; t < 3; t++)
#pragma unroll
                for (int mi = 0; mi < 2; mi++)
#pragma unroll
                    for (int ni = 0; ni < 4; ni++) {
                        const uint32_t (&af)[4] = (t == 2) ? al4[mi] : ah4[mi];
                        const uint32_t b0 = (t == 1) ? bl[ni][0] : bh[ni][0];
                        const uint32_t b1 = (t == 1) ? bl[ni][1] : bh[ni][1];
                        mma16816(acc[mi][ni], af, b0, b1);
                    }
        }
    }

#pragma unroll
    for (int mi = 0; mi < 2; mi++) {
#pragma unroll
        for (int ni = 0; ni < 4; ni++) {
            int row0 = bm + wm + 16 * mi + g;
            int col = bn + wn + 8 * ni + 2 * tig;
            *(float2*)(Cf + (size_t)row0 * DD + col) =
                make_float2(acc[mi][ni][0], acc[mi][ni][1]);
            *(float2*)(Cf + (size_t)(row0 + 8) * DD + col) =
                make_float2(acc[mi][ni][2], acc[mi][ni][3]);
        }
    }
}

// ---------------------------------------------------------------------------
// Flash attention — fp16 single-term (R15 winner, unchanged).
// ---------------------------------------------------------------------------
#define AT_ASZ (64 * 72 * 2)     // 9216
#define AT_STAGE (2 * AT_ASZ)    // 18432 (K, V)
#define ATTN_SMEM (3 * AT_STAGE) // 55296

__global__ __launch_bounds__(128, 3) void attn_mma(
    const __half* __restrict__ q,
    const __half* __restrict__ k,
    const __half* __restrict__ v,
    __nv_bfloat16* __restrict__ oh, __nv_bfloat16* __restrict__ ol) {
    extern __shared__ char smc[];
    const uint32_t smb = smem_u32(smc);
    const int tid = threadIdx.x, lane = tid & 31, wid = tid >> 5;
    const int qt = (int)(gridDim.x - 1 - blockIdx.x);
    const int h = blockIdx.y, b = blockIdx.z;
    const int qbase = qt * 64;
    const int g = lane >> 2, tig = lane & 3;
    const int wrow = 16 * wid;

    {
#pragma unroll
        for (int i = 0; i < 4; i++) {
            int id = i * 128 + tid;
            int row = id >> 3, ch = (id & 7) * 8;
            cpa16(smb + (uint32_t)(row * 72 + ch) * 2,
                  q + (size_t)(b * LL + qbase + row) * DD + h * HD + ch);
        }
    }
    CP_COMMIT();
    cp_wait<0>();
    __syncthreads();

    uint32_t qf[4][4];
#pragma unroll
    for (int j = 0; j < 4; j++) {
        uint32_t off = (uint32_t)(((wrow + (lane & 15)) * 72 +
                                   16 * j + ((lane >> 4) << 3)) * 2);
        ldsm_x4(qf[j], smb + off);
    }
    __syncthreads();

    const __half* gkv = (wid >> 1) ? v : k;
    const int rbase = (wid & 1) * 32;
    auto load_kv = [&](int st, int kb) {
        uint32_t sbase = smb + st * AT_STAGE + (wid >> 1) * AT_ASZ;
#pragma unroll
        for (int i = 0; i < 8; i++) {
            int id = i * 32 + lane;
            int row = rbase + (id >> 3), ch = (id & 7) * 8;
            cpa16(sbase + (uint32_t)(row * 72 + ch) * 2,
                  gkv + (size_t)(b * LL + kb + row) * DD + h * HD + ch);
        }
    };

    const int nkt = qt + 1;
    load_kv(0, 0);
    CP_COMMIT();
    load_kv(1, 64);
    CP_COMMIT();

    float l0 = 0.0f, l1 = 0.0f;
    float o[8][4];
#pragma unroll
    for (int f = 0; f < 8; f++)
#pragma unroll
        for (int r = 0; r < 4; r++) o[f][r] = 0.0f;

    for (int kt = 0; kt < nkt; kt++) {
        cp_wait<1>();
        __syncthreads();

        const int kb = kt * 64;
        const int st = kt % 3;
        const uint32_t sK = smb + st * AT_STAGE;
        const uint32_t sV = sK + AT_ASZ;

        float sf[8][4];
#pragma unroll
        for (int f = 0; f < 8; f++)
#pragma unroll
            for (int r = 0; r < 4; r++) sf[f][r] = 0.0f;

#pragma unroll
        for (int jj = 0; jj < 4; jj++) {
            uint32_t th[4][4];
#pragma unroll
            for (int p = 0; p < 4; p++) {
                uint32_t off = (uint32_t)(((16 * p + ((lane >> 4) << 3) + (lane & 7)) * 72 +
                                           16 * jj + ((lane >> 3) & 1) * 8) * 2);
                ldsm_x4(th[p], sK + off);
            }
#pragma unroll
            for (int p = 0; p < 4; p++) {
                mma16816h(sf[2 * p],     qf[jj], th[p][0], th[p][1]);
                mma16816h(sf[2 * p + 1], qf[jj], th[p][2], th[p][3]);
            }
        }

        if (kt + 2 < nkt) load_kv((kt + 2) % 3, (kt + 2) * 64);
        CP_COMMIT();

        const int row0 = qbase + wrow + g, row1 = row0 + 8;
        if (kb + 63 > qbase + wrow) {
#pragma unroll
            for (int f = 0; f < 8; f++) {
                int col = kb + 8 * f + 2 * tig;
                if (col > row0) sf[f][0] = -1e30f;
                if (col + 1 > row0) sf[f][1] = -1e30f;
                if (col > row1) sf[f][2] = -1e30f;
                if (col + 1 > row1) sf[f][3] = -1e30f;
            }
        }

#pragma unroll
        for (int f = 0; f < 8; f++) {
            sf[f][0] = __expf(sf[f][0]);
            sf[f][1] = __expf(sf[f][1]);
            sf[f][2] = __expf(sf[f][2]);
            sf[f][3] = __expf(sf[f][3]);
            l0 += sf[f][0] + sf[f][1];
            l1 += sf[f][2] + sf[f][3];
        }

#pragma unroll
        for (int j = 0; j < 4; j++) {
            uint32_t pA[4];
            pA[0] = pack2h(sf[2 * j][0], sf[2 * j][1]);
            pA[1] = pack2h(sf[2 * j][2], sf[2 * j][3]);
            pA[2] = pack2h(sf[2 * j + 1][0], sf[2 * j + 1][1]);
            pA[3] = pack2h(sf[2 * j + 1][2], sf[2 * j + 1][3]);
            uint32_t vf[4][4];
#pragma unroll
            for (int p = 0; p < 4; p++) {
                uint32_t off = (uint32_t)(((16 * j + ((lane >> 3) & 1) * 8 + (lane & 7)) * 72 +
                                           16 * p + (lane >> 4) * 8) * 2);
                ldsm_x4_t(vf[p], sV + off);
            }
#pragma unroll
            for (int p = 0; p < 4; p++) {
                mma16816h(o[2 * p],     pA, vf[p][0], vf[p][1]);
                mma16816h(o[2 * p + 1], pA, vf[p][2], vf[p][3]);
            }
        }
    }

    l0 += __shfl_xor_sync(0xffffffffu, l0, 1);
    l0 += __shfl_xor_sync(0xffffffffu, l0, 2);
    l1 += __shfl_xor_sync(0xffffffffu, l1, 1);
    l1 += __shfl_xor_sync(0xffffffffu, l1, 2);
    const float i0 = 1.0f / l0, i1 = 1.0f / l1;
    const size_t grow0 = (size_t)(b * LL + qbase + wrow + g);
    const size_t grow1 = grow0 + 8;
#pragma unroll
    for (int f = 0; f < 8; f++) {
        int col = h * HD + 8 * f + 2 * tig;
        uint32_t hi, lo;
        split_pack(o[f][0] * i0, o[f][1] * i0, hi, lo);
        *(uint32_t*)(oh + grow0 * DD + col) = hi;
        *(uint32_t*)(ol + grow0 * DD + col) = lo;
        split_pack(o[f][2] * i1, o[f][3] * i1, hi, lo);
        *(uint32_t*)(oh + grow1 * DD + col) = hi;
        *(uint32_t*)(ol + grow1 * DD + col) = lo;
    }
}

// ---------------------------------------------------------------------------
// Conversions
// ---------------------------------------------------------------------------
__global__ __launch_bounds__(256) void conv_x16(const float* __restrict__ x,
                                                __half* __restrict__ x16) {
    int i = (blockIdx.x * 256 + threadIdx.x) * 4;
    float4 v = *(const float4*)(x + i);
    __half hh[4] = {__float2half(v.x), __float2half(v.y),
                    __float2half(v.z), __float2half(v.w)};
    *(uint2*)(x16 + i) = *(uint2*)hh;
}

// z 0..2: Wq/Wk/Wv -> transposed fp16 single. z=3: Wo -> transposed bf16 split.
__global__ __launch_bounds__(256) void conv_w4(const float* __restrict__ W0,
                                               const float* __restrict__ W1,
                                               const float* __restrict__ W2,
                                               const float* __restrict__ W3,
                                               __half* __restrict__ T16,
                                               __nv_bfloat16* __restrict__ Twh,
                                               __nv_bfloat16* __restrict__ Twl) {
    __shared__ float t[32][33];
    const int tx = threadIdx.x, ty = threadIdx.y;  // 32 x 8
    const int n0 = blockIdx.x * 32, k0 = blockIdx.y * 32;
    const int z = blockIdx.z;
    const float* W = (z == 0) ? W0 : (z == 1) ? W1 : (z == 2) ? W2 : W3;
#pragma unroll
    for (int j = 0; j < 32; j += 8)
        t[ty + j][tx] = W[(size_t)(k0 + ty + j) * DD + n0 + tx];
    __syncthreads();
    if (z < 3) {
        __half* th = T16 + (size_t)z * DD * DD;
#pragma unroll
        for (int j = 0; j < 32; j += 8)
            th[(size_t)(n0 + ty + j) * DD + k0 + tx] = __float2half(t[tx][ty + j]);
    } else {
#pragma unroll
        for (int j = 0; j < 32; j += 8) {
            float v = t[tx][ty + j];
            __nv_bfloat16 hh = __float2bfloat16(v);
            __nv_bfloat16 ll = __float2bfloat16(v - __bfloat162float(hh));
            Twh[(size_t)(n0 + ty + j) * DD + k0 + tx] = hh;
            Twl[(size_t)(n0 + ty + j) * DD + k0 + tx] = ll;
        }
    }
}

// ---------------------------------------------------------------------------
// Launch
// ---------------------------------------------------------------------------
extern "C" void kernel_launch(void* const* d_in, const int* in_sizes, int n_in,
                              void* d_out, int out_size) {
    const float* x  = (const float*)d_in[0];
    const float* Wk = (const float*)d_in[1];
    const float* Wq = (const float*)d_in[2];
    const float* Wv = (const float*)d_in[3];
    const float* Wo = (const float*)d_in[4];
    float* out = (float*)d_out;

    void *p;
    cudaGetSymbolAddress(&p, g_x16); __half* x16 = (__half*)p;
    cudaGetSymbolAddress(&p, g_w16); __half* w16 = (__half*)p;
    cudaGetSymbolAddress(&p, g_q16); __half* q16 = (__half*)p;
    cudaGetSymbolAddress(&p, g_k16); __half* k16 = (__half*)p;
    cudaGetSymbolAddress(&p, g_v16); __half* v16 = (__half*)p;
    cudaGetSymbolAddress(&p, g_ah);  __nv_bfloat16* ah = (__nv_bfloat16*)p;
    cudaGetSymbolAddress(&p, g_al);  __nv_bfloat16* al = (__nv_bfloat16*)p;
    cudaGetSymbolAddress(&p, g_woh); __nv_bfloat16* woh = (__nv_bfloat16*)p;
    cudaGetSymbolAddress(&p, g_wol); __nv_bfloat16* wol = (__nv_bfloat16*)p;

    static bool attrs_set = false;
    if (!attrs_set) {
        cudaFuncSetAttribute(gemm16, cudaFuncAttributeMaxDynamicSharedMemorySize, GEMM16_SMEM);
        cudaFuncSetAttribute(gemm_bf3, cudaFuncAttributeMaxDynamicSharedMemorySize, GEMM_SMEM);
        cudaFuncSetAttribute(attn_mma, cudaFuncAttributeMaxDynamicSharedMemorySize, ATTN_SMEM);
        attrs_set = true;
    }

    // 1. conversions
    conv_x16<<<MM * DD / (256 * 4), 256>>>(x, x16);
    dim3 wgrid(DD / 32, DD / 32, 4);
    dim3 wblk(32, 8);
    conv_w4<<<wgrid, wblk>>>(Wq, Wk, Wv, Wo, w16, woh, wol);

    // 2. fused QKV projections, single-term fp16 (z: 0=Q*0.125, 1=K, 2=V)
    dim3 ggrid(DD / 64, MM / 128, 3);   // (16, 32, 3)
    gemm16<<<ggrid, 256, GEMM16_SMEM>>>(x16, w16, q16, k16, v16);

    // 3. attention (fp16 single-term; output split-bf16)
    dim3 agrid(LL / 64, HH, BB);  // (32, 16, 2)
    attn_mma<<<agrid, 128, ATTN_SMEM>>>(q16, k16, v16, ah, al);

    // 4. output projection (3-term split-bf16 precision hedge, fp32 out)
    dim3 ogrid(DD / 64, MM / 128, 1);
    gemm_bf3<<<ogrid, 256, GEMM_SMEM>>>(ah, al, woh, wol, out);
}